// round 8
// baseline (speedup 1.0000x reference)
#include <cuda_runtime.h>
#include <cuda_bf16.h>
#include <cstdint>

// ---------------------------------------------------------------------------
// Aligner via mma.sync bf16 (HMMA) with 2-term hi/lo split.
//   ex = ix@W^T+b ; eo = io@W^T+b ; S = ex@eo^T ; P = softmax(S); out = P@io
// fp32 GEMM == 3 bf16 phases accumulated in fp32 registers:
//   A_hi*B_hi + A_hi*B_lo + A_lo*B_hi
// R7: CTA tile 128x256 (8 warps of 64x64), 3-stage cp.async pipeline with a
//     single barrier per chunk, per-chunk resident Ah/Al/Bh/Bl (R6 scheme).
// ---------------------------------------------------------------------------

typedef unsigned short u16;  // raw bf16 bits

// ======================= scratch (device globals) ===========================
__device__ u16   g_ixs [16384L * 2048];     // ix split  [M, hi(0..1023)|lo]
__device__ u16   g_ios [16384L * 2048];     // io split
__device__ u16   g_iosT[32L * 1024 * 1024]; // io^T split per batch [d, m_hi|m_lo]
__device__ u16   g_ws  [1024L * 2048];      // W split
__device__ u16   g_exs [16384L * 2048];     // ex split (proj output)
__device__ u16   g_eos [16384L * 2048];     // eo split
__device__ float g_sc  [32L * 512 * 512];   // scores fp32
__device__ u16   g_ps  [32L * 512 * 1024];  // softmax probs split [l, m_hi|m_lo]

// ======================= PTX helpers ========================================
__device__ __forceinline__ uint32_t smem_u32(const void* p) {
    uint32_t a;
    asm("{ .reg .u64 t; cvta.to.shared.u64 t, %1; cvt.u32.u64 %0, t; }"
        : "=r"(a) : "l"(p));
    return a;
}

__device__ __forceinline__ void cp_async16(uint32_t saddr, const void* gaddr) {
    asm volatile("cp.async.cg.shared.global [%0], [%1], 16;"
                 :: "r"(saddr), "l"(gaddr) : "memory");
}
__device__ __forceinline__ void cp_commit() {
    asm volatile("cp.async.commit_group;" ::: "memory");
}
template <int N>
__device__ __forceinline__ void cp_wait() {
    asm volatile("cp.async.wait_group %0;" :: "n"(N) : "memory");
}

__device__ __forceinline__ void ldsm_x4(uint32_t* r, uint32_t addr) {
    asm volatile("ldmatrix.sync.aligned.m8n8.x4.shared.b16 {%0,%1,%2,%3}, [%4];"
                 : "=r"(r[0]), "=r"(r[1]), "=r"(r[2]), "=r"(r[3]) : "r"(addr));
}

__device__ __forceinline__ void mma_bf16(float* c, const uint32_t* a,
                                         const uint32_t* b) {
    asm volatile(
        "mma.sync.aligned.m16n8k16.row.col.f32.bf16.bf16.f32 "
        "{%0,%1,%2,%3}, {%4,%5,%6,%7}, {%8,%9}, {%0,%1,%2,%3};"
        : "+f"(c[0]), "+f"(c[1]), "+f"(c[2]), "+f"(c[3])
        : "r"(a[0]), "r"(a[1]), "r"(a[2]), "r"(a[3]), "r"(b[0]), "r"(b[1]));
}

// ======================= split helpers ======================================
__device__ __forceinline__ void split2(float v, __nv_bfloat16& h, __nv_bfloat16& l) {
    h = __float2bfloat16(v);
    l = __float2bfloat16(v - __bfloat162float(h));
}

// fp32 [R, C] -> bf16 [R, 2C] (hi | lo). One float4 per thread.
__global__ void __launch_bounds__(256)
split_kernel(const float* __restrict__ in, u16* __restrict__ out, int C)
{
    const long idx = (long)blockIdx.x * 256 + threadIdx.x;
    const long e = idx * 4;
    const long r = e / C;
    const int  c = (int)(e - r * C);
    const float4 v = *reinterpret_cast<const float4*>(in + e);
    __nv_bfloat16 h0, h1, h2, h3, l0, l1, l2, l3;
    split2(v.x, h0, l0); split2(v.y, h1, l1); split2(v.z, h2, l2); split2(v.w, h3, l3);
    __nv_bfloat16* oh = reinterpret_cast<__nv_bfloat16*>(out + r * (2L * C) + c);
    __nv_bfloat16* ol = reinterpret_cast<__nv_bfloat16*>(out + r * (2L * C) + C + c);
    *reinterpret_cast<__nv_bfloat162*>(oh)     = __halves2bfloat162(h0, h1);
    *reinterpret_cast<__nv_bfloat162*>(oh + 2) = __halves2bfloat162(h2, h3);
    *reinterpret_cast<__nv_bfloat162*>(ol)     = __halves2bfloat162(l0, l1);
    *reinterpret_cast<__nv_bfloat162*>(ol + 2) = __halves2bfloat162(l2, l3);
}

// io [32,512,1024] fp32 -> ioT split [32,1024, 512hi|512lo] bf16
__global__ void __launch_bounds__(256)
transpose_split_kernel(const float* __restrict__ in, u16* __restrict__ out)
{
    __shared__ float t[32][33];
    const int b  = blockIdx.z;
    const int d0 = blockIdx.x * 32;
    const int m0 = blockIdx.y * 32;
    const int tx = threadIdx.x & 31;
    const int ty = threadIdx.x >> 5;   // 0..7
    const float* ib = in + (long)b * 512 * 1024;
#pragma unroll
    for (int i = 0; i < 4; i++)
        t[ty + 8 * i][tx] = ib[(long)(m0 + ty + 8 * i) * 1024 + d0 + tx];
    __syncthreads();
    u16* ob = out + (long)b * 1024 * 1024;
#pragma unroll
    for (int i = 0; i < 4; i++) {
        const int d = d0 + ty + 8 * i;
        const int m = m0 + tx;
        __nv_bfloat16 h, l;
        split2(t[tx][ty + 8 * i], h, l);
        *reinterpret_cast<__nv_bfloat16*>(&ob[(long)d * 1024 + m])       = h;
        *reinterpret_cast<__nv_bfloat16*>(&ob[(long)d * 1024 + 512 + m]) = l;
    }
}

// ======================= mma.sync GEMM ======================================
// C[M,N] = A[M, 2K] (*) B[N, 2K]  via 3 bf16 phases, fp32 reg accumulate.
// CTA tile 128x256, k-chunk 32, 8 warps (2Mx4N grid, warp tile 64x64).
// Per chunk: load Ah/Al/Bh/Bl once; 3 phase MMA groups on resident smem.
// 3-stage cp.async pipeline, ONE __syncthreads per chunk. 1 CTA/SM.
// MODE 0: fp32 out to Cf;  MODE 1: bias add + re-split to Cs (hi|lo at loOff).
#define LDS_STRIDE 40                          // 32 + 8 pad elements per row
#define A_TILE_BYTES (128 * LDS_STRIDE * 2)    // 10240 B
#define B_TILE_BYTES (256 * LDS_STRIDE * 2)    // 20480 B
#define STAGE_BYTES (2 * A_TILE_BYTES + 2 * B_TILE_BYTES)  // 61440 B
#define GEMM_SMEM (3 * STAGE_BYTES)            // 184320 B

template <int MODE>
__global__ void __launch_bounds__(256, 1)
gemm_mma(const u16* __restrict__ A, const u16* __restrict__ B,
         const float* __restrict__ bias, float* __restrict__ Cf,
         u16* __restrict__ Cs,
         int K, long sA, long sB, long sC, int ldc, int loOff)
{
    extern __shared__ char dynsmem[];

    const int tid  = threadIdx.x;
    const int wid  = tid >> 5;
    const int lane = tid & 31;

    const long bz = blockIdx.z;
    A += bz * sA;
    B += bz * sB;
    const int row0 = blockIdx.y * 128;
    const int col0 = blockIdx.x * 256;
    const long lda = 2L * K;

    const int nkc = K / 32;

    const uint32_t sbase = smem_u32(dynsmem);
    // stage s at sbase + s*STAGE_BYTES; within: Ah@0, Al@A_TILE,
    // Bh@2*A_TILE, Bl@2*A_TILE+B_TILE

    // copy mapping: row = tid>>2 (0..63), cc = tid&3 (16B units)
    const int cr0 = tid >> 2;
    const int cc  = tid & 3;

    // warp tiling: 2x4 grid of 64x64 warp tiles
    const int warp_m = wid & 1;
    const int warp_n = wid >> 1;

    float acc[4][8][4];
#pragma unroll
    for (int mt = 0; mt < 4; mt++)
#pragma unroll
        for (int nt = 0; nt < 8; nt++)
#pragma unroll
            for (int i = 0; i < 4; i++) acc[mt][nt][i] = 0.0f;

    // per-lane ldmatrix source offsets (element units)
    const int a_row = warp_m * 64 + (lane & 15);
    const int a_colb = (lane >> 4) << 3;
    const int b_row = warp_n * 64 + (lane & 7) + ((lane >> 4) << 3);
    const int b_colb = ((lane >> 3) & 1) << 3;

    auto stage_copy = [&](int s, int kc) {
        const uint32_t sb0 = sbase + (uint32_t)s * STAGE_BYTES;
        const int hoff = kc * 32;
        const int loff = K + kc * 32;
        // A tiles: 128 rows
#pragma unroll
        for (int j = 0; j < 2; j++) {
            const int r = cr0 + 64 * j;
            const uint32_t so = (uint32_t)r * (LDS_STRIDE * 2) + (uint32_t)cc * 16u;
            const u16* arow = A + (long)(row0 + r) * lda + cc * 8;
            cp_async16(sb0 + so, arow + hoff);
            cp_async16(sb0 + A_TILE_BYTES + so, arow + loff);
        }
        // B tiles: 256 rows
#pragma unroll
        for (int j = 0; j < 4; j++) {
            const int r = cr0 + 64 * j;
            const uint32_t so = (uint32_t)r * (LDS_STRIDE * 2) + (uint32_t)cc * 16u;
            const u16* brow = B + (long)(col0 + r) * lda + cc * 8;
            cp_async16(sb0 + 2 * A_TILE_BYTES + so, brow + hoff);
            cp_async16(sb0 + 2 * A_TILE_BYTES + B_TILE_BYTES + so, brow + loff);
        }
        cp_commit();
    };

    // prologue: 2 chunks in flight
    stage_copy(0, 0);
    stage_copy(1, 1);

    for (int kc = 0; kc < nkc; kc++) {
        cp_wait<1>();
        __syncthreads();
        // stage (kc+2)%3 was fully consumed by all warps before this barrier
        if (kc + 2 < nkc) stage_copy((kc + 2) % 3, kc + 2);
        else              cp_commit();   // keep group count advancing

        const uint32_t st = sbase + (uint32_t)(kc % 3) * STAGE_BYTES;
        const uint32_t stAl = st + A_TILE_BYTES;
        const uint32_t stBh = st + 2 * A_TILE_BYTES;
        const uint32_t stBl = stBh + B_TILE_BYTES;
#pragma unroll
        for (int kk = 0; kk < 2; kk++) {
            const uint32_t a_off =
                (uint32_t)a_row * (LDS_STRIDE * 2) + (uint32_t)(kk * 16 + a_colb) * 2;
            const uint32_t b_off =
                (uint32_t)b_row * (LDS_STRIDE * 2) + (uint32_t)(kk * 16 + b_colb) * 2;

            // ---- Ah, Bh frags; phase 1: Ah*Bh ----
            uint32_t ah[4][4];
#pragma unroll
            for (int mt = 0; mt < 4; mt++)
                ldsm_x4(ah[mt], st + a_off + (uint32_t)(mt * 16) * (LDS_STRIDE * 2));
            uint32_t bh[8][2];
#pragma unroll
            for (int nt2 = 0; nt2 < 4; nt2++) {
                uint32_t r4[4];
                ldsm_x4(r4, stBh + b_off + (uint32_t)(nt2 * 16) * (LDS_STRIDE * 2));
                bh[2 * nt2][0] = r4[0]; bh[2 * nt2][1] = r4[1];
                bh[2 * nt2 + 1][0] = r4[2]; bh[2 * nt2 + 1][1] = r4[3];
            }
#pragma unroll
            for (int mt = 0; mt < 4; mt++)
#pragma unroll
                for (int nt = 0; nt < 8; nt++)
                    mma_bf16(acc[mt][nt], ah[mt], bh[nt]);

            // ---- Bl frags; phase 2: Ah*Bl ----
            {
                uint32_t bl[8][2];
#pragma unroll
                for (int nt2 = 0; nt2 < 4; nt2++) {
                    uint32_t r4[4];
                    ldsm_x4(r4, stBl + b_off + (uint32_t)(nt2 * 16) * (LDS_STRIDE * 2));
                    bl[2 * nt2][0] = r4[0]; bl[2 * nt2][1] = r4[1];
                    bl[2 * nt2 + 1][0] = r4[2]; bl[2 * nt2 + 1][1] = r4[3];
                }
#pragma unroll
                for (int mt = 0; mt < 4; mt++)
#pragma unroll
                    for (int nt = 0; nt < 8; nt++)
                        mma_bf16(acc[mt][nt], ah[mt], bl[nt]);
            }

            // ---- Al frags (Ah dead); phase 3: Al*Bh ----
            {
                uint32_t al[4][4];
#pragma unroll
                for (int mt = 0; mt < 4; mt++)
                    ldsm_x4(al[mt], stAl + a_off +
                                    (uint32_t)(mt * 16) * (LDS_STRIDE * 2));
#pragma unroll
                for (int mt = 0; mt < 4; mt++)
#pragma unroll
                    for (int nt = 0; nt < 8; nt++)
                        mma_bf16(acc[mt][nt], al[mt], bh[nt]);
            }
        }
    }

    // ---- epilogue ----
    const int er0 = row0 + warp_m * 64 + (lane >> 2);
    const int ec0 = col0 + warp_n * 64 + (lane & 3) * 2;
#pragma unroll
    for (int mt = 0; mt < 4; mt++) {
#pragma unroll
        for (int nt = 0; nt < 8; nt++) {
            const int r0 = er0 + mt * 16;
            const int r1 = r0 + 8;
            const int c  = ec0 + nt * 8;
            if (MODE == 0) {
                float2 v0, v1;
                v0.x = acc[mt][nt][0]; v0.y = acc[mt][nt][1];
                v1.x = acc[mt][nt][2]; v1.y = acc[mt][nt][3];
                *reinterpret_cast<float2*>(Cf + bz * sC + (long)r0 * ldc + c) = v0;
                *reinterpret_cast<float2*>(Cf + bz * sC + (long)r1 * ldc + c) = v1;
            } else {
                const float b0 = bias[c], b1 = bias[c + 1];
                __nv_bfloat16 h0, h1, l0, l1;
                u16* q0 = Cs + (long)r0 * ldc + c;
                split2(acc[mt][nt][0] + b0, h0, l0);
                split2(acc[mt][nt][1] + b1, h1, l1);
                *reinterpret_cast<__nv_bfloat162*>(q0) = __halves2bfloat162(h0, h1);
                *reinterpret_cast<__nv_bfloat162*>(q0 + loOff) = __halves2bfloat162(l0, l1);
                u16* q1 = Cs + (long)r1 * ldc + c;
                split2(acc[mt][nt][2] + b0, h0, l0);
                split2(acc[mt][nt][3] + b1, h1, l1);
                *reinterpret_cast<__nv_bfloat162*>(q1) = __halves2bfloat162(h0, h1);
                *reinterpret_cast<__nv_bfloat162*>(q1 + loOff) = __halves2bfloat162(l0, l1);
            }
        }
    }
}

// ======================= softmax + split ====================================
__global__ void __launch_bounds__(256)
softmax512_split_kernel(const float* __restrict__ S, u16* __restrict__ P)
{
    __shared__ float red[256];
    const float* row = S + (long)blockIdx.x * 512;
    u16* prow = P + (long)blockIdx.x * 1024;
    const int t = threadIdx.x;

    const float a = row[t];
    const float b = row[t + 256];

    red[t] = fmaxf(a, b);
    __syncthreads();
#pragma unroll
    for (int s = 128; s > 0; s >>= 1) {
        if (t < s) red[t] = fmaxf(red[t], red[t + s]);
        __syncthreads();
    }
    const float mx = red[0];
    __syncthreads();

    const float e0 = __expf(a - mx);
    const float e1 = __expf(b - mx);
    red[t] = e0 + e1;
    __syncthreads();
#pragma unroll
    for (int s = 128; s > 0; s >>= 1) {
        if (t < s) red[t] += red[t + s];
        __syncthreads();
    }
    const float inv = 1.0f / red[0];

    __nv_bfloat16 h, l;
    split2(e0 * inv, h, l);
    *reinterpret_cast<__nv_bfloat16*>(&prow[t])             = h;
    *reinterpret_cast<__nv_bfloat16*>(&prow[512 + t])       = l;
    split2(e1 * inv, h, l);
    *reinterpret_cast<__nv_bfloat16*>(&prow[t + 256])       = h;
    *reinterpret_cast<__nv_bfloat16*>(&prow[512 + t + 256]) = l;
}

// ======================= launch =============================================
extern "C" void kernel_launch(void* const* d_in, const int* in_sizes, int n_in,
                              void* d_out, int out_size)
{
    const float* ix = (const float*)d_in[0];   // [32, 512, 1024]
    const float* io = (const float*)d_in[1];   // [32, 512, 1024]
    const float* W  = (const float*)d_in[2];   // [1024, 1024]
    const float* bi = (const float*)d_in[3];   // [1024]
    float* out = (float*)d_out;                // [32, 512, 1024]

    u16 *ixs, *ios, *iosT, *ws, *exs, *eos, *ps;
    float* sc;
    cudaGetSymbolAddress((void**)&ixs,  g_ixs);
    cudaGetSymbolAddress((void**)&ios,  g_ios);
    cudaGetSymbolAddress((void**)&iosT, g_iosT);
    cudaGetSymbolAddress((void**)&ws,   g_ws);
    cudaGetSymbolAddress((void**)&exs,  g_exs);
    cudaGetSymbolAddress((void**)&eos,  g_eos);
    cudaGetSymbolAddress((void**)&sc,   g_sc);
    cudaGetSymbolAddress((void**)&ps,   g_ps);

    cudaFuncSetAttribute(gemm_mma<0>, cudaFuncAttributeMaxDynamicSharedMemorySize, GEMM_SMEM);
    cudaFuncSetAttribute(gemm_mma<1>, cudaFuncAttributeMaxDynamicSharedMemorySize, GEMM_SMEM);

    const int Bn = 32, L = 512, D = 1024;
    const int Mproj = Bn * L;  // 16384

    // 0) prep kernels ordered so the ncu -s slot lands on a GEMM launch
    split_kernel<<<(D * (long)D) / 1024, 256>>>(W, ws, D);             // 0
    split_kernel<<<(Mproj * (long)D) / 1024, 256>>>(ix, ixs, D);       // 1
    {
        dim3 g(D / 32, L / 32, Bn);
        transpose_split_kernel<<<g, 256>>>(io, iosT);                  // 2
    }

    // 1) projection 1 (captured by ncu)                               // 3
    {
        dim3 g(D / 256, Mproj / 128, 1);
        gemm_mma<1><<<g, 256, GEMM_SMEM>>>(ixs, ws, bi, nullptr, exs, D, 0, 0, 0, 2 * D, D);
    }
    split_kernel<<<(Mproj * (long)D) / 1024, 256>>>(io, ios, D);       // 4
    {
        dim3 g(D / 256, Mproj / 128, 1);
        gemm_mma<1><<<g, 256, GEMM_SMEM>>>(ios, ws, bi, nullptr, eos, D, 0, 0, 0, 2 * D, D);
    }

    // 2) scores: S[b] = ex[b] @ eo[b]^T   (fp32 out)
    {
        dim3 g(L / 256, L / 128, Bn);
        gemm_mma<0><<<g, 256, GEMM_SMEM>>>(exs, eos, nullptr, sc, nullptr,
                                           D, (long)L * 2 * D, (long)L * 2 * D,
                                           (long)L * L, L, 0);
    }

    // 3) softmax + split probs
    softmax512_split_kernel<<<Bn * L, 256>>>(sc, ps);

    // 4) out[b] = P[b] @ ioT[b]^T  (NT with pre-transposed io)
    {
        dim3 g(D / 256, L / 128, Bn);
        gemm_mma<0><<<g, 256, GEMM_SMEM>>>(ps, iosT, nullptr, out, nullptr,
                                           L, (long)L * 2 * L, (long)D * 2 * L,
                                           (long)L * D, D, 0);
    }
}

// round 9
// speedup vs baseline: 1.1616x; 1.1616x over previous
#include <cuda_runtime.h>
#include <cuda_bf16.h>
#include <cstdint>

// ---------------------------------------------------------------------------
// Aligner via mma.sync bf16 (HMMA) with 2-term hi/lo split.
//   ex = ix@W^T+b ; eo = io@W^T+b ; S = ex@eo^T ; P = softmax(S); out = P@io
// fp32 GEMM == 3 bf16 phases accumulated in fp32 registers:
//   A_hi*B_hi + A_hi*B_lo + A_lo*B_hi
// R8: 128x128 tile, 4 warps, 2 CTA/SM (R6 shape) + ONE barrier per chunk +
//     all 16 ldmatrix issued up-front per kk so 96 HMMAs run back-to-back.
// ---------------------------------------------------------------------------

typedef unsigned short u16;  // raw bf16 bits

// ======================= scratch (device globals) ===========================
__device__ u16   g_ixs [16384L * 2048];     // ix split  [M, hi(0..1023)|lo]
__device__ u16   g_ios [16384L * 2048];     // io split
__device__ u16   g_iosT[32L * 1024 * 1024]; // io^T split per batch [d, m_hi|m_lo]
__device__ u16   g_ws  [1024L * 2048];      // W split
__device__ u16   g_exs [16384L * 2048];     // ex split (proj output)
__device__ u16   g_eos [16384L * 2048];     // eo split
__device__ float g_sc  [32L * 512 * 512];   // scores fp32
__device__ u16   g_ps  [32L * 512 * 1024];  // softmax probs split [l, m_hi|m_lo]

// ======================= PTX helpers ========================================
__device__ __forceinline__ uint32_t smem_u32(const void* p) {
    uint32_t a;
    asm("{ .reg .u64 t; cvta.to.shared.u64 t, %1; cvt.u32.u64 %0, t; }"
        : "=r"(a) : "l"(p));
    return a;
}

__device__ __forceinline__ void cp_async16(uint32_t saddr, const void* gaddr) {
    asm volatile("cp.async.cg.shared.global [%0], [%1], 16;"
                 :: "r"(saddr), "l"(gaddr) : "memory");
}
__device__ __forceinline__ void cp_commit() {
    asm volatile("cp.async.commit_group;" ::: "memory");
}
template <int N>
__device__ __forceinline__ void cp_wait() {
    asm volatile("cp.async.wait_group %0;" :: "n"(N) : "memory");
}

__device__ __forceinline__ void ldsm_x4(uint32_t* r, uint32_t addr) {
    asm volatile("ldmatrix.sync.aligned.m8n8.x4.shared.b16 {%0,%1,%2,%3}, [%4];"
                 : "=r"(r[0]), "=r"(r[1]), "=r"(r[2]), "=r"(r[3]) : "r"(addr));
}

__device__ __forceinline__ void mma_bf16(float* c, const uint32_t* a,
                                         const uint32_t* b) {
    asm volatile(
        "mma.sync.aligned.m16n8k16.row.col.f32.bf16.bf16.f32 "
        "{%0,%1,%2,%3}, {%4,%5,%6,%7}, {%8,%9}, {%0,%1,%2,%3};"
        : "+f"(c[0]), "+f"(c[1]), "+f"(c[2]), "+f"(c[3])
        : "r"(a[0]), "r"(a[1]), "r"(a[2]), "r"(a[3]), "r"(b[0]), "r"(b[1]));
}

// ======================= split helpers ======================================
__device__ __forceinline__ void split2(float v, __nv_bfloat16& h, __nv_bfloat16& l) {
    h = __float2bfloat16(v);
    l = __float2bfloat16(v - __bfloat162float(h));
}

// fp32 [R, C] -> bf16 [R, 2C] (hi | lo). One float4 per thread.
__global__ void __launch_bounds__(256)
split_kernel(const float* __restrict__ in, u16* __restrict__ out, int C)
{
    const long idx = (long)blockIdx.x * 256 + threadIdx.x;
    const long e = idx * 4;
    const long r = e / C;
    const int  c = (int)(e - r * C);
    const float4 v = *reinterpret_cast<const float4*>(in + e);
    __nv_bfloat16 h0, h1, h2, h3, l0, l1, l2, l3;
    split2(v.x, h0, l0); split2(v.y, h1, l1); split2(v.z, h2, l2); split2(v.w, h3, l3);
    __nv_bfloat16* oh = reinterpret_cast<__nv_bfloat16*>(out + r * (2L * C) + c);
    __nv_bfloat16* ol = reinterpret_cast<__nv_bfloat16*>(out + r * (2L * C) + C + c);
    *reinterpret_cast<__nv_bfloat162*>(oh)     = __halves2bfloat162(h0, h1);
    *reinterpret_cast<__nv_bfloat162*>(oh + 2) = __halves2bfloat162(h2, h3);
    *reinterpret_cast<__nv_bfloat162*>(ol)     = __halves2bfloat162(l0, l1);
    *reinterpret_cast<__nv_bfloat162*>(ol + 2) = __halves2bfloat162(l2, l3);
}

// io [32,512,1024] fp32 -> ioT split [32,1024, 512hi|512lo] bf16
__global__ void __launch_bounds__(256)
transpose_split_kernel(const float* __restrict__ in, u16* __restrict__ out)
{
    __shared__ float t[32][33];
    const int b  = blockIdx.z;
    const int d0 = blockIdx.x * 32;
    const int m0 = blockIdx.y * 32;
    const int tx = threadIdx.x & 31;
    const int ty = threadIdx.x >> 5;   // 0..7
    const float* ib = in + (long)b * 512 * 1024;
#pragma unroll
    for (int i = 0; i < 4; i++)
        t[ty + 8 * i][tx] = ib[(long)(m0 + ty + 8 * i) * 1024 + d0 + tx];
    __syncthreads();
    u16* ob = out + (long)b * 1024 * 1024;
#pragma unroll
    for (int i = 0; i < 4; i++) {
        const int d = d0 + ty + 8 * i;
        const int m = m0 + tx;
        __nv_bfloat16 h, l;
        split2(t[tx][ty + 8 * i], h, l);
        *reinterpret_cast<__nv_bfloat16*>(&ob[(long)d * 1024 + m])       = h;
        *reinterpret_cast<__nv_bfloat16*>(&ob[(long)d * 1024 + 512 + m]) = l;
    }
}

// ======================= mma.sync GEMM ======================================
// C[M,N] = A[M, 2K] (*) B[N, 2K]  via 3 bf16 phases, fp32 reg accumulate.
// CTA tile 128x128, k-chunk 32, 4 warps (2Mx2N grid, warp tile 64x64).
// Per chunk: load Ah/Al/Bh/Bl once; per kk all 16 ldmatrix up-front, then
// 96 independent HMMAs. 2-stage cp.async pipeline, ONE barrier per chunk.
// 2 CTAs/SM.
// MODE 0: fp32 out to Cf;  MODE 1: bias add + re-split to Cs (hi|lo at loOff).
#define LDS_STRIDE 40                        // 32 + 8 pad elements per row
#define TILE_BYTES (128 * LDS_STRIDE * 2)    // 10240 B per tile
#define STAGE_BYTES (4 * TILE_BYTES)         // Ah,Al,Bh,Bl
#define GEMM_SMEM (2 * STAGE_BYTES)          // 2 stages = 81920 B

template <int MODE>
__global__ void __launch_bounds__(128, 2)
gemm_mma(const u16* __restrict__ A, const u16* __restrict__ B,
         const float* __restrict__ bias, float* __restrict__ Cf,
         u16* __restrict__ Cs,
         int K, long sA, long sB, long sC, int ldc, int loOff)
{
    extern __shared__ char dynsmem[];

    const int tid  = threadIdx.x;
    const int wid  = tid >> 5;
    const int lane = tid & 31;

    const long bz = blockIdx.z;
    A += bz * sA;
    B += bz * sB;
    const int row0 = blockIdx.y * 128;
    const int col0 = blockIdx.x * 128;
    const long lda = 2L * K;

    const int nkc = K / 32;

    const uint32_t sbase = smem_u32(dynsmem);
    // stage s: +s*STAGE_BYTES; tiles within stage: 0=Ah 1=Al 2=Bh 3=Bl

    // copy mapping: row = tid>>2 (0..31), cc = tid&3 (16B units)
    const int cr0 = tid >> 2;
    const int cc  = tid & 3;

    // warp tiling: 2x2 grid of 64x64 warp tiles
    const int warp_m = wid & 1;
    const int warp_n = wid >> 1;

    float acc[4][8][4];
#pragma unroll
    for (int mt = 0; mt < 4; mt++)
#pragma unroll
        for (int nt = 0; nt < 8; nt++)
#pragma unroll
            for (int i = 0; i < 4; i++) acc[mt][nt][i] = 0.0f;

    // per-lane ldmatrix source offsets (element units)
    const int a_row = warp_m * 64 + (lane & 15);
    const int a_colb = (lane >> 4) << 3;
    const int b_row = warp_n * 64 + (lane & 7) + ((lane >> 4) << 3);
    const int b_colb = ((lane >> 3) & 1) << 3;

    auto stage_copy = [&](int s, int kc) {
        const uint32_t sb0 = sbase + (uint32_t)s * STAGE_BYTES;
        const int hoff = kc * 32;
        const int loff = K + kc * 32;
#pragma unroll
        for (int j = 0; j < 4; j++) {
            const int r = cr0 + 32 * j;
            const uint32_t so = (uint32_t)r * (LDS_STRIDE * 2) + (uint32_t)cc * 16u;
            const u16* arow = A + (long)(row0 + r) * lda + cc * 8;
            const u16* brow = B + (long)(col0 + r) * lda + cc * 8;
            cp_async16(sb0 + 0 * TILE_BYTES + so, arow + hoff);
            cp_async16(sb0 + 1 * TILE_BYTES + so, arow + loff);
            cp_async16(sb0 + 2 * TILE_BYTES + so, brow + hoff);
            cp_async16(sb0 + 3 * TILE_BYTES + so, brow + loff);
        }
        cp_commit();
    };

    stage_copy(0, 0);

    for (int kc = 0; kc < nkc; kc++) {
        cp_wait<0>();      // this thread's copies for chunk kc complete
        __syncthreads();   // visible to all; all warps done reading (kc+1)&1
        if (kc + 1 < nkc) stage_copy((kc + 1) & 1, kc + 1);

        const uint32_t st = sbase + (uint32_t)(kc & 1) * STAGE_BYTES;
        const uint32_t stAl = st + 1 * TILE_BYTES;
        const uint32_t stBh = st + 2 * TILE_BYTES;
        const uint32_t stBl = st + 3 * TILE_BYTES;
#pragma unroll
        for (int kk = 0; kk < 2; kk++) {
            const uint32_t a_off =
                (uint32_t)a_row * (LDS_STRIDE * 2) + (uint32_t)(kk * 16 + a_colb) * 2;
            const uint32_t b_off =
                (uint32_t)b_row * (LDS_STRIDE * 2) + (uint32_t)(kk * 16 + b_colb) * 2;

            // ---- issue ALL 16 ldmatrix up-front ----
            uint32_t ah[4][4], al[4][4];
#pragma unroll
            for (int mt = 0; mt < 4; mt++) {
                const uint32_t ao = a_off + (uint32_t)(mt * 16) * (LDS_STRIDE * 2);
                ldsm_x4(ah[mt], st + ao);
                ldsm_x4(al[mt], stAl + ao);
            }
            uint32_t bh[8][2], bl[8][2];
#pragma unroll
            for (int nt2 = 0; nt2 < 4; nt2++) {
                const uint32_t bo = b_off + (uint32_t)(nt2 * 16) * (LDS_STRIDE * 2);
                uint32_t r4[4];
                ldsm_x4(r4, stBh + bo);
                bh[2 * nt2][0] = r4[0]; bh[2 * nt2][1] = r4[1];
                bh[2 * nt2 + 1][0] = r4[2]; bh[2 * nt2 + 1][1] = r4[3];
                uint32_t s4[4];
                ldsm_x4(s4, stBl + bo);
                bl[2 * nt2][0] = s4[0]; bl[2 * nt2][1] = s4[1];
                bl[2 * nt2 + 1][0] = s4[2]; bl[2 * nt2 + 1][1] = s4[3];
            }

            // ---- 96 independent HMMAs ----
#pragma unroll
            for (int mt = 0; mt < 4; mt++)
#pragma unroll
                for (int nt = 0; nt < 8; nt++)
                    mma_bf16(acc[mt][nt], ah[mt], bh[nt]);
#pragma unroll
            for (int mt = 0; mt < 4; mt++)
#pragma unroll
                for (int nt = 0; nt < 8; nt++)
                    mma_bf16(acc[mt][nt], ah[mt], bl[nt]);
#pragma unroll
            for (int mt = 0; mt < 4; mt++)
#pragma unroll
                for (int nt = 0; nt < 8; nt++)
                    mma_bf16(acc[mt][nt], al[mt], bh[nt]);
        }
    }

    // ---- epilogue ----
    const int er0 = row0 + warp_m * 64 + (lane >> 2);
    const int ec0 = col0 + warp_n * 64 + (lane & 3) * 2;
#pragma unroll
    for (int mt = 0; mt < 4; mt++) {
#pragma unroll
        for (int nt = 0; nt < 8; nt++) {
            const int r0 = er0 + mt * 16;
            const int r1 = r0 + 8;
            const int c  = ec0 + nt * 8;
            if (MODE == 0) {
                float2 v0, v1;
                v0.x = acc[mt][nt][0]; v0.y = acc[mt][nt][1];
                v1.x = acc[mt][nt][2]; v1.y = acc[mt][nt][3];
                *reinterpret_cast<float2*>(Cf + bz * sC + (long)r0 * ldc + c) = v0;
                *reinterpret_cast<float2*>(Cf + bz * sC + (long)r1 * ldc + c) = v1;
            } else {
                const float b0 = bias[c], b1 = bias[c + 1];
                __nv_bfloat16 h0, h1, l0, l1;
                u16* q0 = Cs + (long)r0 * ldc + c;
                split2(acc[mt][nt][0] + b0, h0, l0);
                split2(acc[mt][nt][1] + b1, h1, l1);
                *reinterpret_cast<__nv_bfloat162*>(q0) = __halves2bfloat162(h0, h1);
                *reinterpret_cast<__nv_bfloat162*>(q0 + loOff) = __halves2bfloat162(l0, l1);
                u16* q1 = Cs + (long)r1 * ldc + c;
                split2(acc[mt][nt][2] + b0, h0, l0);
                split2(acc[mt][nt][3] + b1, h1, l1);
                *reinterpret_cast<__nv_bfloat162*>(q1) = __halves2bfloat162(h0, h1);
                *reinterpret_cast<__nv_bfloat162*>(q1 + loOff) = __halves2bfloat162(l0, l1);
            }
        }
    }
}

// ======================= softmax + split ====================================
__global__ void __launch_bounds__(256)
softmax512_split_kernel(const float* __restrict__ S, u16* __restrict__ P)
{
    __shared__ float red[256];
    const float* row = S + (long)blockIdx.x * 512;
    u16* prow = P + (long)blockIdx.x * 1024;
    const int t = threadIdx.x;

    const float a = row[t];
    const float b = row[t + 256];

    red[t] = fmaxf(a, b);
    __syncthreads();
#pragma unroll
    for (int s = 128; s > 0; s >>= 1) {
        if (t < s) red[t] = fmaxf(red[t], red[t + s]);
        __syncthreads();
    }
    const float mx = red[0];
    __syncthreads();

    const float e0 = __expf(a - mx);
    const float e1 = __expf(b - mx);
    red[t] = e0 + e1;
    __syncthreads();
#pragma unroll
    for (int s = 128; s > 0; s >>= 1) {
        if (t < s) red[t] += red[t + s];
        __syncthreads();
    }
    const float inv = 1.0f / red[0];

    __nv_bfloat16 h, l;
    split2(e0 * inv, h, l);
    *reinterpret_cast<__nv_bfloat16*>(&prow[t])             = h;
    *reinterpret_cast<__nv_bfloat16*>(&prow[512 + t])       = l;
    split2(e1 * inv, h, l);
    *reinterpret_cast<__nv_bfloat16*>(&prow[t + 256])       = h;
    *reinterpret_cast<__nv_bfloat16*>(&prow[512 + t + 256]) = l;
}

// ======================= launch =============================================
extern "C" void kernel_launch(void* const* d_in, const int* in_sizes, int n_in,
                              void* d_out, int out_size)
{
    const float* ix = (const float*)d_in[0];   // [32, 512, 1024]
    const float* io = (const float*)d_in[1];   // [32, 512, 1024]
    const float* W  = (const float*)d_in[2];   // [1024, 1024]
    const float* bi = (const float*)d_in[3];   // [1024]
    float* out = (float*)d_out;                // [32, 512, 1024]

    u16 *ixs, *ios, *iosT, *ws, *exs, *eos, *ps;
    float* sc;
    cudaGetSymbolAddress((void**)&ixs,  g_ixs);
    cudaGetSymbolAddress((void**)&ios,  g_ios);
    cudaGetSymbolAddress((void**)&iosT, g_iosT);
    cudaGetSymbolAddress((void**)&ws,   g_ws);
    cudaGetSymbolAddress((void**)&exs,  g_exs);
    cudaGetSymbolAddress((void**)&eos,  g_eos);
    cudaGetSymbolAddress((void**)&sc,   g_sc);
    cudaGetSymbolAddress((void**)&ps,   g_ps);

    cudaFuncSetAttribute(gemm_mma<0>, cudaFuncAttributeMaxDynamicSharedMemorySize, GEMM_SMEM);
    cudaFuncSetAttribute(gemm_mma<1>, cudaFuncAttributeMaxDynamicSharedMemorySize, GEMM_SMEM);

    const int Bn = 32, L = 512, D = 1024;
    const int Mproj = Bn * L;  // 16384

    // 0) prep kernels ordered so the ncu -s slot lands on a GEMM launch
    split_kernel<<<(D * (long)D) / 1024, 256>>>(W, ws, D);             // 0
    split_kernel<<<(Mproj * (long)D) / 1024, 256>>>(ix, ixs, D);       // 1
    {
        dim3 g(D / 32, L / 32, Bn);
        transpose_split_kernel<<<g, 256>>>(io, iosT);                  // 2
    }

    // 1) projections (launch #3 and #5; ncu -s 5 captures #5 = proj2)
    {
        dim3 g(D / 128, Mproj / 128, 1);
        gemm_mma<1><<<g, 128, GEMM_SMEM>>>(ixs, ws, bi, nullptr, exs, D, 0, 0, 0, 2 * D, D);
    }
    split_kernel<<<(Mproj * (long)D) / 1024, 256>>>(io, ios, D);       // 4
    {
        dim3 g(D / 128, Mproj / 128, 1);
        gemm_mma<1><<<g, 128, GEMM_SMEM>>>(ios, ws, bi, nullptr, eos, D, 0, 0, 0, 2 * D, D);
    }

    // 2) scores: S[b] = ex[b] @ eo[b]^T   (fp32 out)
    {
        dim3 g(L / 128, L / 128, Bn);
        gemm_mma<0><<<g, 128, GEMM_SMEM>>>(exs, eos, nullptr, sc, nullptr,
                                           D, (long)L * 2 * D, (long)L * 2 * D,
                                           (long)L * L, L, 0);
    }

    // 3) softmax + split probs
    softmax512_split_kernel<<<Bn * L, 256>>>(sc, ps);

    // 4) out[b] = P[b] @ ioT[b]^T  (NT with pre-transposed io)
    {
        dim3 g(D / 128, L / 128, Bn);
        gemm_mma<0><<<g, 128, GEMM_SMEM>>>(ps, iosT, nullptr, out, nullptr,
                                           L, (long)L * 2 * L, (long)D * 2 * L,
                                           (long)L * D, D, 0);
    }
}

// round 10
// speedup vs baseline: 1.1844x; 1.0197x over previous
#include <cuda_runtime.h>
#include <cuda_bf16.h>
#include <cstdint>

// ---------------------------------------------------------------------------
// Aligner via mma.sync bf16 (HMMA) with 2-term hi/lo split.
//   ex = ix@W^T+b ; eo = io@W^T+b ; S = ex@eo^T ; P = softmax(S); out = P@io
// fp32 GEMM == 3 bf16 phases accumulated in fp32 registers:
//   A_hi*B_hi + A_hi*B_lo + A_lo*B_hi
// R9: both projections fused into ONE GEMM (M=32768, no wave-tail waste);
//     chunk body reordered LDSM-first so cp.async doesn't block the MIO
//     queue ahead of ldmatrix.
// ---------------------------------------------------------------------------

typedef unsigned short u16;  // raw bf16 bits

// ======================= scratch (device globals) ===========================
__device__ u16   g_xys [32768L * 2048];     // [ix; io] split  (128 MB)
__device__ u16   g_exys[32768L * 2048];     // [ex; eo] split  (128 MB)
__device__ u16   g_iosT[32L * 1024 * 1024]; // io^T split per batch [d, m_hi|m_lo]
__device__ u16   g_ws  [1024L * 2048];      // W split
__device__ float g_sc  [32L * 512 * 512];   // scores fp32
__device__ u16   g_ps  [32L * 512 * 1024];  // softmax probs split [l, m_hi|m_lo]

// ======================= PTX helpers ========================================
__device__ __forceinline__ uint32_t smem_u32(const void* p) {
    uint32_t a;
    asm("{ .reg .u64 t; cvta.to.shared.u64 t, %1; cvt.u32.u64 %0, t; }"
        : "=r"(a) : "l"(p));
    return a;
}

__device__ __forceinline__ void cp_async16(uint32_t saddr, const void* gaddr) {
    asm volatile("cp.async.cg.shared.global [%0], [%1], 16;"
                 :: "r"(saddr), "l"(gaddr) : "memory");
}
__device__ __forceinline__ void cp_commit() {
    asm volatile("cp.async.commit_group;" ::: "memory");
}
template <int N>
__device__ __forceinline__ void cp_wait() {
    asm volatile("cp.async.wait_group %0;" :: "n"(N) : "memory");
}

__device__ __forceinline__ void ldsm_x4(uint32_t* r, uint32_t addr) {
    asm volatile("ldmatrix.sync.aligned.m8n8.x4.shared.b16 {%0,%1,%2,%3}, [%4];"
                 : "=r"(r[0]), "=r"(r[1]), "=r"(r[2]), "=r"(r[3]) : "r"(addr));
}

__device__ __forceinline__ void mma_bf16(float* c, const uint32_t* a,
                                         const uint32_t* b) {
    asm volatile(
        "mma.sync.aligned.m16n8k16.row.col.f32.bf16.bf16.f32 "
        "{%0,%1,%2,%3}, {%4,%5,%6,%7}, {%8,%9}, {%0,%1,%2,%3};"
        : "+f"(c[0]), "+f"(c[1]), "+f"(c[2]), "+f"(c[3])
        : "r"(a[0]), "r"(a[1]), "r"(a[2]), "r"(a[3]), "r"(b[0]), "r"(b[1]));
}

// ======================= split helpers ======================================
__device__ __forceinline__ void split2(float v, __nv_bfloat16& h, __nv_bfloat16& l) {
    h = __float2bfloat16(v);
    l = __float2bfloat16(v - __bfloat162float(h));
}

// fp32 [R, C] -> bf16 [R, 2C] (hi | lo). One float4 per thread.
__global__ void __launch_bounds__(256)
split_kernel(const float* __restrict__ in, u16* __restrict__ out, int C)
{
    const long idx = (long)blockIdx.x * 256 + threadIdx.x;
    const long e = idx * 4;
    const long r = e / C;
    const int  c = (int)(e - r * C);
    const float4 v = *reinterpret_cast<const float4*>(in + e);
    __nv_bfloat16 h0, h1, h2, h3, l0, l1, l2, l3;
    split2(v.x, h0, l0); split2(v.y, h1, l1); split2(v.z, h2, l2); split2(v.w, h3, l3);
    __nv_bfloat16* oh = reinterpret_cast<__nv_bfloat16*>(out + r * (2L * C) + c);
    __nv_bfloat16* ol = reinterpret_cast<__nv_bfloat16*>(out + r * (2L * C) + C + c);
    *reinterpret_cast<__nv_bfloat162*>(oh)     = __halves2bfloat162(h0, h1);
    *reinterpret_cast<__nv_bfloat162*>(oh + 2) = __halves2bfloat162(h2, h3);
    *reinterpret_cast<__nv_bfloat162*>(ol)     = __halves2bfloat162(l0, l1);
    *reinterpret_cast<__nv_bfloat162*>(ol + 2) = __halves2bfloat162(l2, l3);
}

// io [32,512,1024] fp32 -> ioT split [32,1024, 512hi|512lo] bf16
__global__ void __launch_bounds__(256)
transpose_split_kernel(const float* __restrict__ in, u16* __restrict__ out)
{
    __shared__ float t[32][33];
    const int b  = blockIdx.z;
    const int d0 = blockIdx.x * 32;
    const int m0 = blockIdx.y * 32;
    const int tx = threadIdx.x & 31;
    const int ty = threadIdx.x >> 5;   // 0..7
    const float* ib = in + (long)b * 512 * 1024;
#pragma unroll
    for (int i = 0; i < 4; i++)
        t[ty + 8 * i][tx] = ib[(long)(m0 + ty + 8 * i) * 1024 + d0 + tx];
    __syncthreads();
    u16* ob = out + (long)b * 1024 * 1024;
#pragma unroll
    for (int i = 0; i < 4; i++) {
        const int d = d0 + ty + 8 * i;
        const int m = m0 + tx;
        __nv_bfloat16 h, l;
        split2(t[tx][ty + 8 * i], h, l);
        *reinterpret_cast<__nv_bfloat16*>(&ob[(long)d * 1024 + m])       = h;
        *reinterpret_cast<__nv_bfloat16*>(&ob[(long)d * 1024 + 512 + m]) = l;
    }
}

// ======================= mma.sync GEMM ======================================
// C[M,N] = A[M, 2K] (*) B[N, 2K]  via 3 bf16 phases, fp32 reg accumulate.
// CTA tile 128x128, k-chunk 32, 4 warps (2Mx2N grid, warp tile 64x64).
// Per chunk: LDSM kk=0 frags FIRST, then stage_copy(next) (keeps cp.async
// behind ldmatrix in the MIO queue), then MMAs. 2-stage pipeline, one
// barrier per chunk, 2 CTAs/SM.
// MODE 0: fp32 out to Cf;  MODE 1: bias add + re-split to Cs (hi|lo at loOff).
#define LDS_STRIDE 40                        // 32 + 8 pad elements per row
#define TILE_BYTES (128 * LDS_STRIDE * 2)    // 10240 B per tile
#define STAGE_BYTES (4 * TILE_BYTES)         // Ah,Al,Bh,Bl
#define GEMM_SMEM (2 * STAGE_BYTES)          // 2 stages = 81920 B

template <int MODE>
__global__ void __launch_bounds__(128, 2)
gemm_mma(const u16* __restrict__ A, const u16* __restrict__ B,
         const float* __restrict__ bias, float* __restrict__ Cf,
         u16* __restrict__ Cs,
         int K, long sA, long sB, long sC, int ldc, int loOff)
{
    extern __shared__ char dynsmem[];

    const int tid  = threadIdx.x;
    const int wid  = tid >> 5;
    const int lane = tid & 31;

    const long bz = blockIdx.z;
    A += bz * sA;
    B += bz * sB;
    const int row0 = blockIdx.y * 128;
    const int col0 = blockIdx.x * 128;
    const long lda = 2L * K;

    const int nkc = K / 32;

    const uint32_t sbase = smem_u32(dynsmem);
    // stage s: +s*STAGE_BYTES; tiles within stage: 0=Ah 1=Al 2=Bh 3=Bl

    const int cr0 = tid >> 2;
    const int cc  = tid & 3;

    const int warp_m = wid & 1;
    const int warp_n = wid >> 1;

    float acc[4][8][4];
#pragma unroll
    for (int mt = 0; mt < 4; mt++)
#pragma unroll
        for (int nt = 0; nt < 8; nt++)
#pragma unroll
            for (int i = 0; i < 4; i++) acc[mt][nt][i] = 0.0f;

    const int a_row = warp_m * 64 + (lane & 15);
    const int a_colb = (lane >> 4) << 3;
    const int b_row = warp_n * 64 + (lane & 7) + ((lane >> 4) << 3);
    const int b_colb = ((lane >> 3) & 1) << 3;

    auto stage_copy = [&](int s, int kc) {
        const uint32_t sb0 = sbase + (uint32_t)s * STAGE_BYTES;
        const int hoff = kc * 32;
        const int loff = K + kc * 32;
#pragma unroll
        for (int j = 0; j < 4; j++) {
            const int r = cr0 + 32 * j;
            const uint32_t so = (uint32_t)r * (LDS_STRIDE * 2) + (uint32_t)cc * 16u;
            const u16* arow = A + (long)(row0 + r) * lda + cc * 8;
            const u16* brow = B + (long)(col0 + r) * lda + cc * 8;
            cp_async16(sb0 + 0 * TILE_BYTES + so, arow + hoff);
            cp_async16(sb0 + 1 * TILE_BYTES + so, arow + loff);
            cp_async16(sb0 + 2 * TILE_BYTES + so, brow + hoff);
            cp_async16(sb0 + 3 * TILE_BYTES + so, brow + loff);
        }
        cp_commit();
    };

    stage_copy(0, 0);

    for (int kc = 0; kc < nkc; kc++) {
        cp_wait<0>();
        __syncthreads();

        const uint32_t st = sbase + (uint32_t)(kc & 1) * STAGE_BYTES;
        const uint32_t stAl = st + 1 * TILE_BYTES;
        const uint32_t stBh = st + 2 * TILE_BYTES;
        const uint32_t stBl = st + 3 * TILE_BYTES;

        // ---- kk = 0: LDSM first (ahead of cp.async in the MIO queue) ----
        uint32_t ah[4][4], al[4][4], bh[8][2], bl[8][2];
        {
            const uint32_t a_off =
                (uint32_t)a_row * (LDS_STRIDE * 2) + (uint32_t)a_colb * 2;
            const uint32_t b_off =
                (uint32_t)b_row * (LDS_STRIDE * 2) + (uint32_t)b_colb * 2;
#pragma unroll
            for (int mt = 0; mt < 4; mt++) {
                const uint32_t ao = a_off + (uint32_t)(mt * 16) * (LDS_STRIDE * 2);
                ldsm_x4(ah[mt], st + ao);
                ldsm_x4(al[mt], stAl + ao);
            }
#pragma unroll
            for (int nt2 = 0; nt2 < 4; nt2++) {
                const uint32_t bo = b_off + (uint32_t)(nt2 * 16) * (LDS_STRIDE * 2);
                uint32_t r4[4];
                ldsm_x4(r4, stBh + bo);
                bh[2 * nt2][0] = r4[0]; bh[2 * nt2][1] = r4[1];
                bh[2 * nt2 + 1][0] = r4[2]; bh[2 * nt2 + 1][1] = r4[3];
                uint32_t s4[4];
                ldsm_x4(s4, stBl + bo);
                bl[2 * nt2][0] = s4[0]; bl[2 * nt2][1] = s4[1];
                bl[2 * nt2 + 1][0] = s4[2]; bl[2 * nt2 + 1][1] = s4[3];
            }
        }

        // ---- now queue the next chunk's copies ----
        if (kc + 1 < nkc) stage_copy((kc + 1) & 1, kc + 1);

        // ---- kk = 0 MMAs ----
#pragma unroll
        for (int mt = 0; mt < 4; mt++)
#pragma unroll
            for (int nt = 0; nt < 8; nt++)
                mma_bf16(acc[mt][nt], ah[mt], bh[nt]);
#pragma unroll
        for (int mt = 0; mt < 4; mt++)
#pragma unroll
            for (int nt = 0; nt < 8; nt++)
                mma_bf16(acc[mt][nt], ah[mt], bl[nt]);
#pragma unroll
        for (int mt = 0; mt < 4; mt++)
#pragma unroll
            for (int nt = 0; nt < 8; nt++)
                mma_bf16(acc[mt][nt], al[mt], bh[nt]);

        // ---- kk = 1: LDSM then MMAs ----
        {
            const uint32_t a_off =
                (uint32_t)a_row * (LDS_STRIDE * 2) + (uint32_t)(16 + a_colb) * 2;
            const uint32_t b_off =
                (uint32_t)b_row * (LDS_STRIDE * 2) + (uint32_t)(16 + b_colb) * 2;
#pragma unroll
            for (int mt = 0; mt < 4; mt++) {
                const uint32_t ao = a_off + (uint32_t)(mt * 16) * (LDS_STRIDE * 2);
                ldsm_x4(ah[mt], st + ao);
                ldsm_x4(al[mt], stAl + ao);
            }
#pragma unroll
            for (int nt2 = 0; nt2 < 4; nt2++) {
                const uint32_t bo = b_off + (uint32_t)(nt2 * 16) * (LDS_STRIDE * 2);
                uint32_t r4[4];
                ldsm_x4(r4, stBh + bo);
                bh[2 * nt2][0] = r4[0]; bh[2 * nt2][1] = r4[1];
                bh[2 * nt2 + 1][0] = r4[2]; bh[2 * nt2 + 1][1] = r4[3];
                uint32_t s4[4];
                ldsm_x4(s4, stBl + bo);
                bl[2 * nt2][0] = s4[0]; bl[2 * nt2][1] = s4[1];
                bl[2 * nt2 + 1][0] = s4[2]; bl[2 * nt2 + 1][1] = s4[3];
            }
        }
#pragma unroll
        for (int mt = 0; mt < 4; mt++)
#pragma unroll
            for (int nt = 0; nt < 8; nt++)
                mma_bf16(acc[mt][nt], ah[mt], bh[nt]);
#pragma unroll
        for (int mt = 0; mt < 4; mt++)
#pragma unroll
            for (int nt = 0; nt < 8; nt++)
                mma_bf16(acc[mt][nt], ah[mt], bl[nt]);
#pragma unroll
        for (int mt = 0; mt < 4; mt++)
#pragma unroll
            for (int nt = 0; nt < 8; nt++)
                mma_bf16(acc[mt][nt], al[mt], bh[nt]);
    }

    // ---- epilogue ----
    const int er0 = row0 + warp_m * 64 + (lane >> 2);
    const int ec0 = col0 + warp_n * 64 + (lane & 3) * 2;
#pragma unroll
    for (int mt = 0; mt < 4; mt++) {
#pragma unroll
        for (int nt = 0; nt < 8; nt++) {
            const int r0 = er0 + mt * 16;
            const int r1 = r0 + 8;
            const int c  = ec0 + nt * 8;
            if (MODE == 0) {
                float2 v0, v1;
                v0.x = acc[mt][nt][0]; v0.y = acc[mt][nt][1];
                v1.x = acc[mt][nt][2]; v1.y = acc[mt][nt][3];
                *reinterpret_cast<float2*>(Cf + bz * sC + (long)r0 * ldc + c) = v0;
                *reinterpret_cast<float2*>(Cf + bz * sC + (long)r1 * ldc + c) = v1;
            } else {
                const float b0 = bias[c], b1 = bias[c + 1];
                __nv_bfloat16 h0, h1, l0, l1;
                u16* q0 = Cs + (long)r0 * ldc + c;
                split2(acc[mt][nt][0] + b0, h0, l0);
                split2(acc[mt][nt][1] + b1, h1, l1);
                *reinterpret_cast<__nv_bfloat162*>(q0) = __halves2bfloat162(h0, h1);
                *reinterpret_cast<__nv_bfloat162*>(q0 + loOff) = __halves2bfloat162(l0, l1);
                u16* q1 = Cs + (long)r1 * ldc + c;
                split2(acc[mt][nt][2] + b0, h0, l0);
                split2(acc[mt][nt][3] + b1, h1, l1);
                *reinterpret_cast<__nv_bfloat162*>(q1) = __halves2bfloat162(h0, h1);
                *reinterpret_cast<__nv_bfloat162*>(q1 + loOff) = __halves2bfloat162(l0, l1);
            }
        }
    }
}

// ======================= softmax + split ====================================
__global__ void __launch_bounds__(256)
softmax512_split_kernel(const float* __restrict__ S, u16* __restrict__ P)
{
    __shared__ float red[256];
    const float* row = S + (long)blockIdx.x * 512;
    u16* prow = P + (long)blockIdx.x * 1024;
    const int t = threadIdx.x;

    const float a = row[t];
    const float b = row[t + 256];

    red[t] = fmaxf(a, b);
    __syncthreads();
#pragma unroll
    for (int s = 128; s > 0; s >>= 1) {
        if (t < s) red[t] = fmaxf(red[t], red[t + s]);
        __syncthreads();
    }
    const float mx = red[0];
    __syncthreads();

    const float e0 = __expf(a - mx);
    const float e1 = __expf(b - mx);
    red[t] = e0 + e1;
    __syncthreads();
#pragma unroll
    for (int s = 128; s > 0; s >>= 1) {
        if (t < s) red[t] += red[t + s];
        __syncthreads();
    }
    const float inv = 1.0f / red[0];

    __nv_bfloat16 h, l;
    split2(e0 * inv, h, l);
    *reinterpret_cast<__nv_bfloat16*>(&prow[t])             = h;
    *reinterpret_cast<__nv_bfloat16*>(&prow[512 + t])       = l;
    split2(e1 * inv, h, l);
    *reinterpret_cast<__nv_bfloat16*>(&prow[t + 256])       = h;
    *reinterpret_cast<__nv_bfloat16*>(&prow[512 + t + 256]) = l;
}

// ======================= launch =============================================
extern "C" void kernel_launch(void* const* d_in, const int* in_sizes, int n_in,
                              void* d_out, int out_size)
{
    const float* ix = (const float*)d_in[0];   // [32, 512, 1024]
    const float* io = (const float*)d_in[1];   // [32, 512, 1024]
    const float* W  = (const float*)d_in[2];   // [1024, 1024]
    const float* bi = (const float*)d_in[3];   // [1024]
    float* out = (float*)d_out;                // [32, 512, 1024]

    u16 *xys, *exys, *iosT, *ws, *ps;
    float* sc;
    cudaGetSymbolAddress((void**)&xys,  g_xys);
    cudaGetSymbolAddress((void**)&exys, g_exys);
    cudaGetSymbolAddress((void**)&iosT, g_iosT);
    cudaGetSymbolAddress((void**)&ws,   g_ws);
    cudaGetSymbolAddress((void**)&sc,   g_sc);
    cudaGetSymbolAddress((void**)&ps,   g_ps);

    cudaFuncSetAttribute(gemm_mma<0>, cudaFuncAttributeMaxDynamicSharedMemorySize, GEMM_SMEM);
    cudaFuncSetAttribute(gemm_mma<1>, cudaFuncAttributeMaxDynamicSharedMemorySize, GEMM_SMEM);

    const int Bn = 32, L = 512, D = 1024;
    const int Mproj = Bn * L;          // 16384 rows per side
    const long halfRows = (long)Mproj * 2 * D;   // u16 offset of io-half

    // 0-2) splits: [ix ; io] into one buffer (fused projection input)
    split_kernel<<<(D * (long)D) / 1024, 256>>>(W, ws, D);                  // 0
    split_kernel<<<(Mproj * (long)D) / 1024, 256>>>(ix, xys, D);            // 1
    split_kernel<<<(Mproj * (long)D) / 1024, 256>>>(io, xys + halfRows, D); // 2

    // 3) fused projection: [ex; eo] = [ix; io] @ W^T + b  (M = 32768)
    {
        dim3 g(D / 128, (2 * Mproj) / 128, 1);
        gemm_mma<1><<<g, 128, GEMM_SMEM>>>(xys, ws, bi, nullptr, exys,
                                           D, 0, 0, 0, 2 * D, D);
    }

    // 4) io^T split (needed only by PV)
    {
        dim3 g(D / 32, L / 32, Bn);
        transpose_split_kernel<<<g, 256>>>(io, iosT);
    }

    // 5) scores: S[b] = ex[b] @ eo[b]^T   (fp32 out)  <-- ncu -s 5 captures this
    {
        dim3 g(L / 128, L / 128, Bn);
        gemm_mma<0><<<g, 128, GEMM_SMEM>>>(exys, exys + halfRows, nullptr, sc, nullptr,
                                           D, (long)L * 2 * D, (long)L * 2 * D,
                                           (long)L * L, L, 0);
    }

    // 6) softmax + split probs
    softmax512_split_kernel<<<Bn * L, 256>>>(sc, ps);

    // 7) out[b] = P[b] @ ioT[b]^T  (NT with pre-transposed io)
    {
        dim3 g(D / 128, L / 128, Bn);
        gemm_mma<0><<<g, 128, GEMM_SMEM>>>(ps, iosT, nullptr, out, nullptr,
                                           L, (long)L * 2 * L, (long)D * 2 * L,
                                           (long)L * D, D, 0);
    }
}

// round 11
// speedup vs baseline: 1.4604x; 1.2330x over previous
#include <cuda_runtime.h>
#include <cuda_bf16.h>
#include <cstdint>

// ---------------------------------------------------------------------------
// Aligner, algebraically restructured (R10):
//   softmax(ex@eo^T) == softmax(ix@(W^T W)@io^T + 1 v^T)   [row-constant terms
//   u, b^Tb drop under row softmax],  v = io @ (W^T b)
//   out = softmax(...) @ io        (ex / eo never materialized)
// GEMM chain (all mma.sync bf16, 2-term hi/lo split, 3 phases):
//   M = W^T W (split out) ; T = ix M (split out) ; S = T io^T (+v in softmax)
//   P = softmax(S+v) ; out = P io
// Total MACs 106 G vs 154.5 G for the explicit-projection formulation.
// ---------------------------------------------------------------------------

typedef unsigned short u16;  // raw bf16 bits

// ======================= scratch (device globals) ===========================
__device__ u16   g_wts [1024L * 2048];      // W^T split [d, e_hi|e_lo]
__device__ u16   g_ms  [1024L * 2048];      // M = W^T W split [d, d'_hi|d'_lo]
__device__ u16   g_ixs [16384L * 2048];     // ix split
__device__ u16   g_ios [16384L * 2048];     // io split
__device__ u16   g_ts  [16384L * 2048];     // T = ix M split
__device__ u16   g_iosT[32L * 1024 * 1024]; // io^T split per batch [d, m_hi|m_lo]
__device__ float g_sc  [32L * 512 * 512];   // scores fp32
__device__ u16   g_ps  [32L * 512 * 1024];  // softmax probs split [l, m_hi|m_lo]
__device__ float g_wtb [1024];              // W^T b
__device__ float g_v   [16384];             // io @ (W^T b)   [b*512 + m]

// ======================= PTX helpers ========================================
__device__ __forceinline__ uint32_t smem_u32(const void* p) {
    uint32_t a;
    asm("{ .reg .u64 t; cvta.to.shared.u64 t, %1; cvt.u32.u64 %0, t; }"
        : "=r"(a) : "l"(p));
    return a;
}

__device__ __forceinline__ void cp_async16(uint32_t saddr, const void* gaddr) {
    asm volatile("cp.async.cg.shared.global [%0], [%1], 16;"
                 :: "r"(saddr), "l"(gaddr) : "memory");
}
__device__ __forceinline__ void cp_commit() {
    asm volatile("cp.async.commit_group;" ::: "memory");
}
template <int N>
__device__ __forceinline__ void cp_wait() {
    asm volatile("cp.async.wait_group %0;" :: "n"(N) : "memory");
}

__device__ __forceinline__ void ldsm_x4(uint32_t* r, uint32_t addr) {
    asm volatile("ldmatrix.sync.aligned.m8n8.x4.shared.b16 {%0,%1,%2,%3}, [%4];"
                 : "=r"(r[0]), "=r"(r[1]), "=r"(r[2]), "=r"(r[3]) : "r"(addr));
}

__device__ __forceinline__ void mma_bf16(float* c, const uint32_t* a,
                                         const uint32_t* b) {
    asm volatile(
        "mma.sync.aligned.m16n8k16.row.col.f32.bf16.bf16.f32 "
        "{%0,%1,%2,%3}, {%4,%5,%6,%7}, {%8,%9}, {%0,%1,%2,%3};"
        : "+f"(c[0]), "+f"(c[1]), "+f"(c[2]), "+f"(c[3])
        : "r"(a[0]), "r"(a[1]), "r"(a[2]), "r"(a[3]), "r"(b[0]), "r"(b[1]));
}

// ======================= split helpers ======================================
__device__ __forceinline__ void split2(float v, __nv_bfloat16& h, __nv_bfloat16& l) {
    h = __float2bfloat16(v);
    l = __float2bfloat16(v - __bfloat162float(h));
}

// fp32 [R, C] -> bf16 [R, 2C] (hi | lo). One float4 per thread.
__global__ void __launch_bounds__(256)
split_kernel(const float* __restrict__ in, u16* __restrict__ out, int C)
{
    const long idx = (long)blockIdx.x * 256 + threadIdx.x;
    const long e = idx * 4;
    const long r = e / C;
    const int  c = (int)(e - r * C);
    const float4 v = *reinterpret_cast<const float4*>(in + e);
    __nv_bfloat16 h0, h1, h2, h3, l0, l1, l2, l3;
    split2(v.x, h0, l0); split2(v.y, h1, l1); split2(v.z, h2, l2); split2(v.w, h3, l3);
    __nv_bfloat16* oh = reinterpret_cast<__nv_bfloat16*>(out + r * (2L * C) + c);
    __nv_bfloat16* ol = reinterpret_cast<__nv_bfloat16*>(out + r * (2L * C) + C + c);
    *reinterpret_cast<__nv_bfloat162*>(oh)     = __halves2bfloat162(h0, h1);
    *reinterpret_cast<__nv_bfloat162*>(oh + 2) = __halves2bfloat162(h2, h3);
    *reinterpret_cast<__nv_bfloat162*>(ol)     = __halves2bfloat162(l0, l1);
    *reinterpret_cast<__nv_bfloat162*>(ol + 2) = __halves2bfloat162(l2, l3);
}

// generic transpose+split: in [R, C] fp32 (batch stride sIn) ->
// out [C, 2R] bf16 split (batch stride sOut).  grid (C/32, R/32, B), 256 thr.
__global__ void __launch_bounds__(256)
transpose_split_kernel(const float* __restrict__ in, u16* __restrict__ out,
                       int R, int C, long sIn, long sOut)
{
    __shared__ float t[32][33];
    const int b  = blockIdx.z;
    const int d0 = blockIdx.x * 32;   // input col
    const int m0 = blockIdx.y * 32;   // input row
    const int tx = threadIdx.x & 31;
    const int ty = threadIdx.x >> 5;   // 0..7
    const float* ib = in + (long)b * sIn;
#pragma unroll
    for (int i = 0; i < 4; i++)
        t[ty + 8 * i][tx] = ib[(long)(m0 + ty + 8 * i) * C + d0 + tx];
    __syncthreads();
    u16* ob = out + (long)b * sOut;
#pragma unroll
    for (int i = 0; i < 4; i++) {
        const int d = d0 + ty + 8 * i;
        const int m = m0 + tx;
        __nv_bfloat16 h, l;
        split2(t[tx][ty + 8 * i], h, l);
        *reinterpret_cast<__nv_bfloat16*>(&ob[(long)d * (2 * R) + m])     = h;
        *reinterpret_cast<__nv_bfloat16*>(&ob[(long)d * (2 * R) + R + m]) = l;
    }
}

// wtb[d] = sum_e W[e,d] * b[e].  grid 32 blocks x 256 thr (32 d x 8 e-lanes).
__global__ void __launch_bounds__(256)
wtb_kernel(const float* __restrict__ W, const float* __restrict__ b,
           float* __restrict__ wtb)
{
    __shared__ float red[8][32];
    const int tx = threadIdx.x & 31;   // d within block
    const int ty = threadIdx.x >> 5;   // e lane
    const int d  = blockIdx.x * 32 + tx;
    float acc = 0.0f;
    for (int e = ty; e < 1024; e += 8)
        acc += W[(long)e * 1024 + d] * b[e];
    red[ty][tx] = acc;
    __syncthreads();
    if (ty == 0) {
        float s = red[0][tx];
#pragma unroll
        for (int i = 1; i < 8; i++) s += red[i][tx];
        wtb[d] = s;
    }
}

// v[r] = sum_d io[r,d] * wtb[d].  one block (256 thr) per row.
__global__ void __launch_bounds__(256)
v_kernel(const float* __restrict__ io, const float* __restrict__ wtb,
         float* __restrict__ v)
{
    __shared__ float red[256];
    const float* row = io + (long)blockIdx.x * 1024;
    const int t = threadIdx.x;
    const float4 a = *reinterpret_cast<const float4*>(row + t * 4);
    const float4 w = *reinterpret_cast<const float4*>(wtb + t * 4);
    red[t] = a.x * w.x + a.y * w.y + a.z * w.z + a.w * w.w;
    __syncthreads();
#pragma unroll
    for (int s = 128; s > 0; s >>= 1) {
        if (t < s) red[t] += red[t + s];
        __syncthreads();
    }
    if (t == 0) v[blockIdx.x] = red[0];
}

// ======================= mma.sync GEMM (R9 engine) ==========================
// C[M,N] = A[M, 2K] (*) B[N, 2K]  via 3 bf16 phases, fp32 reg accumulate.
// CTA tile 128x128, k-chunk 32, 4 warps (2Mx2N, warp tile 64x64), 2 CTA/SM.
// MODE 0: fp32 out to Cf;  MODE 1: (optional bias) + re-split to Cs.
#define LDS_STRIDE 40
#define TILE_BYTES (128 * LDS_STRIDE * 2)
#define STAGE_BYTES (4 * TILE_BYTES)
#define GEMM_SMEM (2 * STAGE_BYTES)

template <int MODE>
__global__ void __launch_bounds__(128, 2)
gemm_mma(const u16* __restrict__ A, const u16* __restrict__ B,
         const float* __restrict__ bias, float* __restrict__ Cf,
         u16* __restrict__ Cs,
         int K, long sA, long sB, long sC, int ldc, int loOff)
{
    extern __shared__ char dynsmem[];

    const int tid  = threadIdx.x;
    const int wid  = tid >> 5;
    const int lane = tid & 31;

    const long bz = blockIdx.z;
    A += bz * sA;
    B += bz * sB;
    const int row0 = blockIdx.y * 128;
    const int col0 = blockIdx.x * 128;
    const long lda = 2L * K;

    const int nkc = K / 32;

    const uint32_t sbase = smem_u32(dynsmem);

    const int cr0 = tid >> 2;
    const int cc  = tid & 3;

    const int warp_m = wid & 1;
    const int warp_n = wid >> 1;

    float acc[4][8][4];
#pragma unroll
    for (int mt = 0; mt < 4; mt++)
#pragma unroll
        for (int nt = 0; nt < 8; nt++)
#pragma unroll
            for (int i = 0; i < 4; i++) acc[mt][nt][i] = 0.0f;

    const int a_row = warp_m * 64 + (lane & 15);
    const int a_colb = (lane >> 4) << 3;
    const int b_row = warp_n * 64 + (lane & 7) + ((lane >> 4) << 3);
    const int b_colb = ((lane >> 3) & 1) << 3;

    auto stage_copy = [&](int s, int kc) {
        const uint32_t sb0 = sbase + (uint32_t)s * STAGE_BYTES;
        const int hoff = kc * 32;
        const int loff = K + kc * 32;
#pragma unroll
        for (int j = 0; j < 4; j++) {
            const int r = cr0 + 32 * j;
            const uint32_t so = (uint32_t)r * (LDS_STRIDE * 2) + (uint32_t)cc * 16u;
            const u16* arow = A + (long)(row0 + r) * lda + cc * 8;
            const u16* brow = B + (long)(col0 + r) * lda + cc * 8;
            cp_async16(sb0 + 0 * TILE_BYTES + so, arow + hoff);
            cp_async16(sb0 + 1 * TILE_BYTES + so, arow + loff);
            cp_async16(sb0 + 2 * TILE_BYTES + so, brow + hoff);
            cp_async16(sb0 + 3 * TILE_BYTES + so, brow + loff);
        }
        cp_commit();
    };

    stage_copy(0, 0);

    for (int kc = 0; kc < nkc; kc++) {
        cp_wait<0>();
        __syncthreads();

        const uint32_t st = sbase + (uint32_t)(kc & 1) * STAGE_BYTES;
        const uint32_t stAl = st + 1 * TILE_BYTES;
        const uint32_t stBh = st + 2 * TILE_BYTES;
        const uint32_t stBl = st + 3 * TILE_BYTES;

        uint32_t ah[4][4], al[4][4], bh[8][2], bl[8][2];
        {
            const uint32_t a_off =
                (uint32_t)a_row * (LDS_STRIDE * 2) + (uint32_t)a_colb * 2;
            const uint32_t b_off =
                (uint32_t)b_row * (LDS_STRIDE * 2) + (uint32_t)b_colb * 2;
#pragma unroll
            for (int mt = 0; mt < 4; mt++) {
                const uint32_t ao = a_off + (uint32_t)(mt * 16) * (LDS_STRIDE * 2);
                ldsm_x4(ah[mt], st + ao);
                ldsm_x4(al[mt], stAl + ao);
            }
#pragma unroll
            for (int nt2 = 0; nt2 < 4; nt2++) {
                const uint32_t bo = b_off + (uint32_t)(nt2 * 16) * (LDS_STRIDE * 2);
                uint32_t r4[4];
                ldsm_x4(r4, stBh + bo);
                bh[2 * nt2][0] = r4[0]; bh[2 * nt2][1] = r4[1];
                bh[2 * nt2 + 1][0] = r4[2]; bh[2 * nt2 + 1][1] = r4[3];
                uint32_t s4[4];
                ldsm_x4(s4, stBl + bo);
                bl[2 * nt2][0] = s4[0]; bl[2 * nt2][1] = s4[1];
                bl[2 * nt2 + 1][0] = s4[2]; bl[2 * nt2 + 1][1] = s4[3];
            }
        }

        if (kc + 1 < nkc) stage_copy((kc + 1) & 1, kc + 1);

#pragma unroll
        for (int mt = 0; mt < 4; mt++)
#pragma unroll
            for (int nt = 0; nt < 8; nt++)
                mma_bf16(acc[mt][nt], ah[mt], bh[nt]);
#pragma unroll
        for (int mt = 0; mt < 4; mt++)
#pragma unroll
            for (int nt = 0; nt < 8; nt++)
                mma_bf16(acc[mt][nt], ah[mt], bl[nt]);
#pragma unroll
        for (int mt = 0; mt < 4; mt++)
#pragma unroll
            for (int nt = 0; nt < 8; nt++)
                mma_bf16(acc[mt][nt], al[mt], bh[nt]);

        {
            const uint32_t a_off =
                (uint32_t)a_row * (LDS_STRIDE * 2) + (uint32_t)(16 + a_colb) * 2;
            const uint32_t b_off =
                (uint32_t)b_row * (LDS_STRIDE * 2) + (uint32_t)(16 + b_colb) * 2;
#pragma unroll
            for (int mt = 0; mt < 4; mt++) {
                const uint32_t ao = a_off + (uint32_t)(mt * 16) * (LDS_STRIDE * 2);
                ldsm_x4(ah[mt], st + ao);
                ldsm_x4(al[mt], stAl + ao);
            }
#pragma unroll
            for (int nt2 = 0; nt2 < 4; nt2++) {
                const uint32_t bo = b_off + (uint32_t)(nt2 * 16) * (LDS_STRIDE * 2);
                uint32_t r4[4];
                ldsm_x4(r4, stBh + bo);
                bh[2 * nt2][0] = r4[0]; bh[2 * nt2][1] = r4[1];
                bh[2 * nt2 + 1][0] = r4[2]; bh[2 * nt2 + 1][1] = r4[3];
                uint32_t s4[4];
                ldsm_x4(s4, stBl + bo);
                bl[2 * nt2][0] = s4[0]; bl[2 * nt2][1] = s4[1];
                bl[2 * nt2 + 1][0] = s4[2]; bl[2 * nt2 + 1][1] = s4[3];
            }
        }
#pragma unroll
        for (int mt = 0; mt < 4; mt++)
#pragma unroll
            for (int nt = 0; nt < 8; nt++)
                mma_bf16(acc[mt][nt], ah[mt], bh[nt]);
#pragma unroll
        for (int mt = 0; mt < 4; mt++)
#pragma unroll
            for (int nt = 0; nt < 8; nt++)
                mma_bf16(acc[mt][nt], ah[mt], bl[nt]);
#pragma unroll
        for (int mt = 0; mt < 4; mt++)
#pragma unroll
            for (int nt = 0; nt < 8; nt++)
                mma_bf16(acc[mt][nt], al[mt], bh[nt]);
    }

    // ---- epilogue ----
    const int er0 = row0 + warp_m * 64 + (lane >> 2);
    const int ec0 = col0 + warp_n * 64 + (lane & 3) * 2;
#pragma unroll
    for (int mt = 0; mt < 4; mt++) {
#pragma unroll
        for (int nt = 0; nt < 8; nt++) {
            const int r0 = er0 + mt * 16;
            const int r1 = r0 + 8;
            const int c  = ec0 + nt * 8;
            if (MODE == 0) {
                float2 v0, v1;
                v0.x = acc[mt][nt][0]; v0.y = acc[mt][nt][1];
                v1.x = acc[mt][nt][2]; v1.y = acc[mt][nt][3];
                *reinterpret_cast<float2*>(Cf + bz * sC + (long)r0 * ldc + c) = v0;
                *reinterpret_cast<float2*>(Cf + bz * sC + (long)r1 * ldc + c) = v1;
            } else {
                const float b0 = bias ? bias[c] : 0.0f;
                const float b1 = bias ? bias[c + 1] : 0.0f;
                __nv_bfloat16 h0, h1, l0, l1;
                u16* q0 = Cs + (long)r0 * ldc + c;
                split2(acc[mt][nt][0] + b0, h0, l0);
                split2(acc[mt][nt][1] + b1, h1, l1);
                *reinterpret_cast<__nv_bfloat162*>(q0) = __halves2bfloat162(h0, h1);
                *reinterpret_cast<__nv_bfloat162*>(q0 + loOff) = __halves2bfloat162(l0, l1);
                u16* q1 = Cs + (long)r1 * ldc + c;
                split2(acc[mt][nt][2] + b0, h0, l0);
                split2(acc[mt][nt][3] + b1, h1, l1);
                *reinterpret_cast<__nv_bfloat162*>(q1) = __halves2bfloat162(h0, h1);
                *reinterpret_cast<__nv_bfloat162*>(q1 + loOff) = __halves2bfloat162(l0, l1);
            }
        }
    }
}

// ======================= softmax(+v) + split ================================
// row of S gets v[m] added per column before softmax (the surviving bias term)
__global__ void __launch_bounds__(256)
softmax512_split_kernel(const float* __restrict__ S, const float* __restrict__ v,
                        u16* __restrict__ P)
{
    __shared__ float red[256];
    const float* row = S + (long)blockIdx.x * 512;
    const float* vb  = v + ((blockIdx.x >> 9) << 9);   // batch base (L = 512)
    u16* prow = P + (long)blockIdx.x * 1024;
    const int t = threadIdx.x;

    const float a = row[t] + vb[t];
    const float b = row[t + 256] + vb[t + 256];

    red[t] = fmaxf(a, b);
    __syncthreads();
#pragma unroll
    for (int s = 128; s > 0; s >>= 1) {
        if (t < s) red[t] = fmaxf(red[t], red[t + s]);
        __syncthreads();
    }
    const float mx = red[0];
    __syncthreads();

    const float e0 = __expf(a - mx);
    const float e1 = __expf(b - mx);
    red[t] = e0 + e1;
    __syncthreads();
#pragma unroll
    for (int s = 128; s > 0; s >>= 1) {
        if (t < s) red[t] += red[t + s];
        __syncthreads();
    }
    const float inv = 1.0f / red[0];

    __nv_bfloat16 h, l;
    split2(e0 * inv, h, l);
    *reinterpret_cast<__nv_bfloat16*>(&prow[t])             = h;
    *reinterpret_cast<__nv_bfloat16*>(&prow[512 + t])       = l;
    split2(e1 * inv, h, l);
    *reinterpret_cast<__nv_bfloat16*>(&prow[t + 256])       = h;
    *reinterpret_cast<__nv_bfloat16*>(&prow[512 + t + 256]) = l;
}

// ======================= launch =============================================
extern "C" void kernel_launch(void* const* d_in, const int* in_sizes, int n_in,
                              void* d_out, int out_size)
{
    const float* ix = (const float*)d_in[0];   // [32, 512, 1024]
    const float* io = (const float*)d_in[1];   // [32, 512, 1024]
    const float* W  = (const float*)d_in[2];   // [1024, 1024]
    const float* bi = (const float*)d_in[3];   // [1024]
    float* out = (float*)d_out;                // [32, 512, 1024]

    u16 *wts, *ms, *ixs, *ios, *ts, *iosT, *ps;
    float *sc, *wtb, *v;
    cudaGetSymbolAddress((void**)&wts,  g_wts);
    cudaGetSymbolAddress((void**)&ms,   g_ms);
    cudaGetSymbolAddress((void**)&ixs,  g_ixs);
    cudaGetSymbolAddress((void**)&ios,  g_ios);
    cudaGetSymbolAddress((void**)&ts,   g_ts);
    cudaGetSymbolAddress((void**)&iosT, g_iosT);
    cudaGetSymbolAddress((void**)&sc,   g_sc);
    cudaGetSymbolAddress((void**)&ps,   g_ps);
    cudaGetSymbolAddress((void**)&wtb,  g_wtb);
    cudaGetSymbolAddress((void**)&v,    g_v);

    cudaFuncSetAttribute(gemm_mma<0>, cudaFuncAttributeMaxDynamicSharedMemorySize, GEMM_SMEM);
    cudaFuncSetAttribute(gemm_mma<1>, cudaFuncAttributeMaxDynamicSharedMemorySize, GEMM_SMEM);

    const int Bn = 32, L = 512, D = 1024;
    const int Mproj = Bn * L;  // 16384

    // 0) W^T split (rows d, cols e)  -- for M = W^T W
    {
        dim3 g(D / 32, D / 32, 1);
        transpose_split_kernel<<<g, 256>>>(W, wts, D, D, 0, 0);
    }
    // 1) wtb = W^T b
    wtb_kernel<<<32, 256>>>(W, bi, wtb);
    // 2-3) input splits
    split_kernel<<<(Mproj * (long)D) / 1024, 256>>>(ix, ixs, D);
    split_kernel<<<(Mproj * (long)D) / 1024, 256>>>(io, ios, D);
    // 4) M = W^T W  (split output, no bias)
    {
        dim3 g(D / 128, D / 128, 1);
        gemm_mma<1><<<g, 128, GEMM_SMEM>>>(wts, wts, nullptr, nullptr, ms,
                                           D, 0, 0, 0, 2 * D, D);
    }
    // 5) T = ix @ M  (M symmetric -> NT GEMM; split output)   [ncu slot 5]
    {
        dim3 g(D / 128, Mproj / 128, 1);
        gemm_mma<1><<<g, 128, GEMM_SMEM>>>(ixs, ms, nullptr, nullptr, ts,
                                           D, 0, 0, 0, 2 * D, D);
    }
    // 6) v = io @ wtb
    v_kernel<<<Mproj, 256>>>(io, wtb, v);
    // 7) S[b] = T[b] @ io[b]^T  (fp32 out; v added in softmax)
    {
        dim3 g(L / 128, L / 128, Bn);
        gemm_mma<0><<<g, 128, GEMM_SMEM>>>(ts, ios, nullptr, sc, nullptr,
                                           D, (long)L * 2 * D, (long)L * 2 * D,
                                           (long)L * L, L, 0);
    }
    // 8) io^T split per batch (for PV)
    {
        dim3 g(D / 32, L / 32, Bn);
        transpose_split_kernel<<<g, 256>>>(io, iosT, L, D,
                                           (long)L * D, (long)D * 2 * L / 2 * 2);
    }
    // 9) softmax(S + v) + split probs
    softmax512_split_kernel<<<Bn * L, 256>>>(sc, v, ps);
    // 10) out[b] = P[b] @ ioT[b]^T
    {
        dim3 g(D / 128, L / 128, Bn);
        gemm_mma<0><<<g, 128, GEMM_SMEM>>>(ps, iosT, nullptr, out, nullptr,
                                           L, (long)L * 2 * L, (long)D * 2 * L,
                                           (long)L * D, D, 0);
    }
}

// round 12
// speedup vs baseline: 1.6600x; 1.1367x over previous
#include <cuda_runtime.h>
#include <cuda_bf16.h>
#include <cstdint>

// ---------------------------------------------------------------------------
// Aligner, algebraic form (R10) + split-K M-GEMM + warp softmax (R11):
//   softmax(ex@eo^T) == softmax(ix@(W^T W)@io^T + 1 v^T),  v = io @ (W^T b)
//   out = softmax(...) @ io
// Chain: M = W^T W (split-K over 4 z-slices, fp32 partials, reduce+split)
//        T = ix M ; S = T io^T ; P = softmax(S+v) ; out = P io
// All GEMMs: mma.sync bf16, 2-term hi/lo split, 3 phases, fp32 accumulate.
// ---------------------------------------------------------------------------

typedef unsigned short u16;  // raw bf16 bits

// ======================= scratch (device globals) ===========================
__device__ u16   g_wts [1024L * 2048];      // W^T split [d, e_hi|e_lo]
__device__ float g_mp  [4L * 1024 * 1024];  // M split-K partials (fp32)
__device__ u16   g_ms  [1024L * 2048];      // M = W^T W split
__device__ u16   g_ixs [16384L * 2048];     // ix split
__device__ u16   g_ios [16384L * 2048];     // io split
__device__ u16   g_ts  [16384L * 2048];     // T = ix M split
__device__ u16   g_iosT[32L * 1024 * 1024]; // io^T split per batch
__device__ float g_sc  [32L * 512 * 512];   // scores fp32
__device__ u16   g_ps  [32L * 512 * 1024];  // softmax probs split
__device__ float g_wtb [1024];              // W^T b
__device__ float g_v   [16384];             // io @ (W^T b)

// ======================= PTX helpers ========================================
__device__ __forceinline__ uint32_t smem_u32(const void* p) {
    uint32_t a;
    asm("{ .reg .u64 t; cvta.to.shared.u64 t, %1; cvt.u32.u64 %0, t; }"
        : "=r"(a) : "l"(p));
    return a;
}

__device__ __forceinline__ void cp_async16(uint32_t saddr, const void* gaddr) {
    asm volatile("cp.async.cg.shared.global [%0], [%1], 16;"
                 :: "r"(saddr), "l"(gaddr) : "memory");
}
__device__ __forceinline__ void cp_commit() {
    asm volatile("cp.async.commit_group;" ::: "memory");
}
template <int N>
__device__ __forceinline__ void cp_wait() {
    asm volatile("cp.async.wait_group %0;" :: "n"(N) : "memory");
}

__device__ __forceinline__ void ldsm_x4(uint32_t* r, uint32_t addr) {
    asm volatile("ldmatrix.sync.aligned.m8n8.x4.shared.b16 {%0,%1,%2,%3}, [%4];"
                 : "=r"(r[0]), "=r"(r[1]), "=r"(r[2]), "=r"(r[3]) : "r"(addr));
}

__device__ __forceinline__ void mma_bf16(float* c, const uint32_t* a,
                                         const uint32_t* b) {
    asm volatile(
        "mma.sync.aligned.m16n8k16.row.col.f32.bf16.bf16.f32 "
        "{%0,%1,%2,%3}, {%4,%5,%6,%7}, {%8,%9}, {%0,%1,%2,%3};"
        : "+f"(c[0]), "+f"(c[1]), "+f"(c[2]), "+f"(c[3])
        : "r"(a[0]), "r"(a[1]), "r"(a[2]), "r"(a[3]), "r"(b[0]), "r"(b[1]));
}

// ======================= split helpers ======================================
__device__ __forceinline__ void split2(float v, __nv_bfloat16& h, __nv_bfloat16& l) {
    h = __float2bfloat16(v);
    l = __float2bfloat16(v - __bfloat162float(h));
}

// fp32 [R, C] -> bf16 [R, 2C] (hi | lo). One float4 per thread.
__global__ void __launch_bounds__(256)
split_kernel(const float* __restrict__ in, u16* __restrict__ out, int C)
{
    const long idx = (long)blockIdx.x * 256 + threadIdx.x;
    const long e = idx * 4;
    const long r = e / C;
    const int  c = (int)(e - r * C);
    const float4 v = *reinterpret_cast<const float4*>(in + e);
    __nv_bfloat16 h0, h1, h2, h3, l0, l1, l2, l3;
    split2(v.x, h0, l0); split2(v.y, h1, l1); split2(v.z, h2, l2); split2(v.w, h3, l3);
    __nv_bfloat16* oh = reinterpret_cast<__nv_bfloat16*>(out + r * (2L * C) + c);
    __nv_bfloat16* ol = reinterpret_cast<__nv_bfloat16*>(out + r * (2L * C) + C + c);
    *reinterpret_cast<__nv_bfloat162*>(oh)     = __halves2bfloat162(h0, h1);
    *reinterpret_cast<__nv_bfloat162*>(oh + 2) = __halves2bfloat162(h2, h3);
    *reinterpret_cast<__nv_bfloat162*>(ol)     = __halves2bfloat162(l0, l1);
    *reinterpret_cast<__nv_bfloat162*>(ol + 2) = __halves2bfloat162(l2, l3);
}

// generic transpose+split: in [R, C] fp32 (batch stride sIn) ->
// out [C, 2R] bf16 split (batch stride sOut).  grid (C/32, R/32, B), 256 thr.
__global__ void __launch_bounds__(256)
transpose_split_kernel(const float* __restrict__ in, u16* __restrict__ out,
                       int R, int C, long sIn, long sOut)
{
    __shared__ float t[32][33];
    const int b  = blockIdx.z;
    const int d0 = blockIdx.x * 32;
    const int m0 = blockIdx.y * 32;
    const int tx = threadIdx.x & 31;
    const int ty = threadIdx.x >> 5;
    const float* ib = in + (long)b * sIn;
#pragma unroll
    for (int i = 0; i < 4; i++)
        t[ty + 8 * i][tx] = ib[(long)(m0 + ty + 8 * i) * C + d0 + tx];
    __syncthreads();
    u16* ob = out + (long)b * sOut;
#pragma unroll
    for (int i = 0; i < 4; i++) {
        const int d = d0 + ty + 8 * i;
        const int m = m0 + tx;
        __nv_bfloat16 h, l;
        split2(t[tx][ty + 8 * i], h, l);
        *reinterpret_cast<__nv_bfloat16*>(&ob[(long)d * (2 * R) + m])     = h;
        *reinterpret_cast<__nv_bfloat16*>(&ob[(long)d * (2 * R) + R + m]) = l;
    }
}

// wtb[d] = sum_e W[e,d] * b[e].
__global__ void __launch_bounds__(256)
wtb_kernel(const float* __restrict__ W, const float* __restrict__ b,
           float* __restrict__ wtb)
{
    __shared__ float red[8][32];
    const int tx = threadIdx.x & 31;
    const int ty = threadIdx.x >> 5;
    const int d  = blockIdx.x * 32 + tx;
    float acc = 0.0f;
    for (int e = ty; e < 1024; e += 8)
        acc += W[(long)e * 1024 + d] * b[e];
    red[ty][tx] = acc;
    __syncthreads();
    if (ty == 0) {
        float s = red[0][tx];
#pragma unroll
        for (int i = 1; i < 8; i++) s += red[i][tx];
        wtb[d] = s;
    }
}

// v[r] = sum_d io[r,d] * wtb[d].
__global__ void __launch_bounds__(256)
v_kernel(const float* __restrict__ io, const float* __restrict__ wtb,
         float* __restrict__ v)
{
    __shared__ float red[256];
    const float* row = io + (long)blockIdx.x * 1024;
    const int t = threadIdx.x;
    const float4 a = *reinterpret_cast<const float4*>(row + t * 4);
    const float4 w = *reinterpret_cast<const float4*>(wtb + t * 4);
    red[t] = a.x * w.x + a.y * w.y + a.z * w.z + a.w * w.w;
    __syncthreads();
#pragma unroll
    for (int s = 128; s > 0; s >>= 1) {
        if (t < s) red[t] += red[t + s];
        __syncthreads();
    }
    if (t == 0) v[blockIdx.x] = red[0];
}

// sum 4 split-K partials of M and split to bf16 hi/lo. one float4 per thread.
__global__ void __launch_bounds__(256)
reduce4_split_kernel(const float* __restrict__ p, u16* __restrict__ out)
{
    const long e = ((long)blockIdx.x * 256 + threadIdx.x) * 4;
    const long r = e >> 10;            // row (C = 1024)
    const int  c = (int)(e & 1023);
    float4 a = *reinterpret_cast<const float4*>(p + e);
    const float4 a1 = *reinterpret_cast<const float4*>(p + 1048576 + e);
    const float4 a2 = *reinterpret_cast<const float4*>(p + 2097152 + e);
    const float4 a3 = *reinterpret_cast<const float4*>(p + 3145728 + e);
    a.x += a1.x + a2.x + a3.x;
    a.y += a1.y + a2.y + a3.y;
    a.z += a1.z + a2.z + a3.z;
    a.w += a1.w + a2.w + a3.w;
    __nv_bfloat16 h0, h1, h2, h3, l0, l1, l2, l3;
    split2(a.x, h0, l0); split2(a.y, h1, l1); split2(a.z, h2, l2); split2(a.w, h3, l3);
    u16* oh = out + r * 2048 + c;
    u16* ol = oh + 1024;
    *reinterpret_cast<__nv_bfloat162*>(oh)     = __halves2bfloat162(h0, h1);
    *reinterpret_cast<__nv_bfloat162*>(oh + 2) = __halves2bfloat162(h2, h3);
    *reinterpret_cast<__nv_bfloat162*>(ol)     = __halves2bfloat162(l0, l1);
    *reinterpret_cast<__nv_bfloat162*>(ol + 2) = __halves2bfloat162(l2, l3);
}

// ======================= mma.sync GEMM engine ===============================
// C[M,N] = A[M, 2*Kfull] (*) B[N, 2*Kfull] over K columns starting at
// kbase = blockIdx.z * kPerZ.  3 bf16 phases, fp32 accumulate.
// CTA tile 128x128, 4 warps (2Mx2N of 64x64), 2-stage cp.async, 2 CTA/SM.
// MODE 0: fp32 out to Cf;  MODE 1: (optional bias) + re-split to Cs.
#define LDS_STRIDE 40
#define TILE_BYTES (128 * LDS_STRIDE * 2)
#define STAGE_BYTES (4 * TILE_BYTES)
#define GEMM_SMEM (2 * STAGE_BYTES)

template <int MODE>
__global__ void __launch_bounds__(128, 2)
gemm_mma(const u16* __restrict__ A, const u16* __restrict__ B,
         const float* __restrict__ bias, float* __restrict__ Cf,
         u16* __restrict__ Cs,
         int K, int Kfull, int kPerZ,
         long sA, long sB, long sC, int ldc, int loOff)
{
    extern __shared__ char dynsmem[];

    const int tid  = threadIdx.x;
    const int wid  = tid >> 5;
    const int lane = tid & 31;

    const long bz = blockIdx.z;
    A += bz * sA;
    B += bz * sB;
    const int kbase = (int)bz * kPerZ;
    const int row0 = blockIdx.y * 128;
    const int col0 = blockIdx.x * 128;
    const long lda = 2L * Kfull;

    const int nkc = K / 32;

    const uint32_t sbase = smem_u32(dynsmem);

    const int cr0 = tid >> 2;
    const int cc  = tid & 3;

    const int warp_m = wid & 1;
    const int warp_n = wid >> 1;

    float acc[4][8][4];
#pragma unroll
    for (int mt = 0; mt < 4; mt++)
#pragma unroll
        for (int nt = 0; nt < 8; nt++)
#pragma unroll
            for (int i = 0; i < 4; i++) acc[mt][nt][i] = 0.0f;

    const int a_row = warp_m * 64 + (lane & 15);
    const int a_colb = (lane >> 4) << 3;
    const int b_row = warp_n * 64 + (lane & 7) + ((lane >> 4) << 3);
    const int b_colb = ((lane >> 3) & 1) << 3;

    auto stage_copy = [&](int s, int kc) {
        const uint32_t sb0 = sbase + (uint32_t)s * STAGE_BYTES;
        const int hoff = kbase + kc * 32;
        const int loff = Kfull + kbase + kc * 32;
#pragma unroll
        for (int j = 0; j < 4; j++) {
            const int r = cr0 + 32 * j;
            const uint32_t so = (uint32_t)r * (LDS_STRIDE * 2) + (uint32_t)cc * 16u;
            const u16* arow = A + (long)(row0 + r) * lda + cc * 8;
            const u16* brow = B + (long)(col0 + r) * lda + cc * 8;
            cp_async16(sb0 + 0 * TILE_BYTES + so, arow + hoff);
            cp_async16(sb0 + 1 * TILE_BYTES + so, arow + loff);
            cp_async16(sb0 + 2 * TILE_BYTES + so, brow + hoff);
            cp_async16(sb0 + 3 * TILE_BYTES + so, brow + loff);
        }
        cp_commit();
    };

    stage_copy(0, 0);

    for (int kc = 0; kc < nkc; kc++) {
        cp_wait<0>();
        __syncthreads();

        const uint32_t st = sbase + (uint32_t)(kc & 1) * STAGE_BYTES;
        const uint32_t stAl = st + 1 * TILE_BYTES;
        const uint32_t stBh = st + 2 * TILE_BYTES;
        const uint32_t stBl = st + 3 * TILE_BYTES;

        uint32_t ah[4][4], al[4][4], bh[8][2], bl[8][2];
        {
            const uint32_t a_off =
                (uint32_t)a_row * (LDS_STRIDE * 2) + (uint32_t)a_colb * 2;
            const uint32_t b_off =
                (uint32_t)b_row * (LDS_STRIDE * 2) + (uint32_t)b_colb * 2;
#pragma unroll
            for (int mt = 0; mt < 4; mt++) {
                const uint32_t ao = a_off + (uint32_t)(mt * 16) * (LDS_STRIDE * 2);
                ldsm_x4(ah[mt], st + ao);
                ldsm_x4(al[mt], stAl + ao);
            }
#pragma unroll
            for (int nt2 = 0; nt2 < 4; nt2++) {
                const uint32_t bo = b_off + (uint32_t)(nt2 * 16) * (LDS_STRIDE * 2);
                uint32_t r4[4];
                ldsm_x4(r4, stBh + bo);
                bh[2 * nt2][0] = r4[0]; bh[2 * nt2][1] = r4[1];
                bh[2 * nt2 + 1][0] = r4[2]; bh[2 * nt2 + 1][1] = r4[3];
                uint32_t s4[4];
                ldsm_x4(s4, stBl + bo);
                bl[2 * nt2][0] = s4[0]; bl[2 * nt2][1] = s4[1];
                bl[2 * nt2 + 1][0] = s4[2]; bl[2 * nt2 + 1][1] = s4[3];
            }
        }

        if (kc + 1 < nkc) stage_copy((kc + 1) & 1, kc + 1);

#pragma unroll
        for (int mt = 0; mt < 4; mt++)
#pragma unroll
            for (int nt = 0; nt < 8; nt++)
                mma_bf16(acc[mt][nt], ah[mt], bh[nt]);
#pragma unroll
        for (int mt = 0; mt < 4; mt++)
#pragma unroll
            for (int nt = 0; nt < 8; nt++)
                mma_bf16(acc[mt][nt], ah[mt], bl[nt]);
#pragma unroll
        for (int mt = 0; mt < 4; mt++)
#pragma unroll
            for (int nt = 0; nt < 8; nt++)
                mma_bf16(acc[mt][nt], al[mt], bh[nt]);

        {
            const uint32_t a_off =
                (uint32_t)a_row * (LDS_STRIDE * 2) + (uint32_t)(16 + a_colb) * 2;
            const uint32_t b_off =
                (uint32_t)b_row * (LDS_STRIDE * 2) + (uint32_t)(16 + b_colb) * 2;
#pragma unroll
            for (int mt = 0; mt < 4; mt++) {
                const uint32_t ao = a_off + (uint32_t)(mt * 16) * (LDS_STRIDE * 2);
                ldsm_x4(ah[mt], st + ao);
                ldsm_x4(al[mt], stAl + ao);
            }
#pragma unroll
            for (int nt2 = 0; nt2 < 4; nt2++) {
                const uint32_t bo = b_off + (uint32_t)(nt2 * 16) * (LDS_STRIDE * 2);
                uint32_t r4[4];
                ldsm_x4(r4, stBh + bo);
                bh[2 * nt2][0] = r4[0]; bh[2 * nt2][1] = r4[1];
                bh[2 * nt2 + 1][0] = r4[2]; bh[2 * nt2 + 1][1] = r4[3];
                uint32_t s4[4];
                ldsm_x4(s4, stBl + bo);
                bl[2 * nt2][0] = s4[0]; bl[2 * nt2][1] = s4[1];
                bl[2 * nt2 + 1][0] = s4[2]; bl[2 * nt2 + 1][1] = s4[3];
            }
        }
#pragma unroll
        for (int mt = 0; mt < 4; mt++)
#pragma unroll
            for (int nt = 0; nt < 8; nt++)
                mma_bf16(acc[mt][nt], ah[mt], bh[nt]);
#pragma unroll
        for (int mt = 0; mt < 4; mt++)
#pragma unroll
            for (int nt = 0; nt < 8; nt++)
                mma_bf16(acc[mt][nt], ah[mt], bl[nt]);
#pragma unroll
        for (int mt = 0; mt < 4; mt++)
#pragma unroll
            for (int nt = 0; nt < 8; nt++)
                mma_bf16(acc[mt][nt], al[mt], bh[nt]);
    }

    // ---- epilogue ----
    const int er0 = row0 + warp_m * 64 + (lane >> 2);
    const int ec0 = col0 + warp_n * 64 + (lane & 3) * 2;
#pragma unroll
    for (int mt = 0; mt < 4; mt++) {
#pragma unroll
        for (int nt = 0; nt < 8; nt++) {
            const int r0 = er0 + mt * 16;
            const int r1 = r0 + 8;
            const int c  = ec0 + nt * 8;
            if (MODE == 0) {
                float2 v0, v1;
                v0.x = acc[mt][nt][0]; v0.y = acc[mt][nt][1];
                v1.x = acc[mt][nt][2]; v1.y = acc[mt][nt][3];
                *reinterpret_cast<float2*>(Cf + bz * sC + (long)r0 * ldc + c) = v0;
                *reinterpret_cast<float2*>(Cf + bz * sC + (long)r1 * ldc + c) = v1;
            } else {
                const float b0 = bias ? bias[c] : 0.0f;
                const float b1 = bias ? bias[c + 1] : 0.0f;
                __nv_bfloat16 h0, h1, l0, l1;
                u16* q0 = Cs + (long)r0 * ldc + c;
                split2(acc[mt][nt][0] + b0, h0, l0);
                split2(acc[mt][nt][1] + b1, h1, l1);
                *reinterpret_cast<__nv_bfloat162*>(q0) = __halves2bfloat162(h0, h1);
                *reinterpret_cast<__nv_bfloat162*>(q0 + loOff) = __halves2bfloat162(l0, l1);
                u16* q1 = Cs + (long)r1 * ldc + c;
                split2(acc[mt][nt][2] + b0, h0, l0);
                split2(acc[mt][nt][3] + b1, h1, l1);
                *reinterpret_cast<__nv_bfloat162*>(q1) = __halves2bfloat162(h0, h1);
                *reinterpret_cast<__nv_bfloat162*>(q1 + loOff) = __halves2bfloat162(l0, l1);
            }
        }
    }
}

// ======================= warp softmax(+v) + split ===========================
// One warp per 512-wide row, shfl-only reductions, float4 I/O.
__global__ void __launch_bounds__(256)
softmax512_split_warp(const float* __restrict__ S, const float* __restrict__ v,
                      u16* __restrict__ P)
{
    const int gw   = (blockIdx.x * 256 + threadIdx.x) >> 5;   // row id
    const int lane = threadIdx.x & 31;
    const float* row = S + (long)gw * 512;
    const float* vb  = v + ((gw >> 9) << 9);
    u16* prow = P + (long)gw * 1024;

    float x[16];
    float mx = -1e30f;
#pragma unroll
    for (int i = 0; i < 4; i++) {
        const int c = i * 128 + lane * 4;
        const float4 a = *reinterpret_cast<const float4*>(row + c);
        const float4 w = *reinterpret_cast<const float4*>(vb + c);
        x[4 * i + 0] = a.x + w.x;
        x[4 * i + 1] = a.y + w.y;
        x[4 * i + 2] = a.z + w.z;
        x[4 * i + 3] = a.w + w.w;
        mx = fmaxf(mx, fmaxf(fmaxf(x[4 * i], x[4 * i + 1]),
                             fmaxf(x[4 * i + 2], x[4 * i + 3])));
    }
#pragma unroll
    for (int o = 16; o > 0; o >>= 1)
        mx = fmaxf(mx, __shfl_xor_sync(0xFFFFFFFFu, mx, o));

    float sum = 0.0f;
#pragma unroll
    for (int j = 0; j < 16; j++) {
        x[j] = __expf(x[j] - mx);
        sum += x[j];
    }
#pragma unroll
    for (int o = 16; o > 0; o >>= 1)
        sum += __shfl_xor_sync(0xFFFFFFFFu, sum, o);
    const float inv = 1.0f / sum;

#pragma unroll
    for (int i = 0; i < 4; i++) {
        const int c = i * 128 + lane * 4;
        __nv_bfloat16 h0, h1, h2, h3, l0, l1, l2, l3;
        split2(x[4 * i + 0] * inv, h0, l0);
        split2(x[4 * i + 1] * inv, h1, l1);
        split2(x[4 * i + 2] * inv, h2, l2);
        split2(x[4 * i + 3] * inv, h3, l3);
        u16* oh = prow + c;
        u16* ol = prow + 512 + c;
        *reinterpret_cast<__nv_bfloat162*>(oh)     = __halves2bfloat162(h0, h1);
        *reinterpret_cast<__nv_bfloat162*>(oh + 2) = __halves2bfloat162(h2, h3);
        *reinterpret_cast<__nv_bfloat162*>(ol)     = __halves2bfloat162(l0, l1);
        *reinterpret_cast<__nv_bfloat162*>(ol + 2) = __halves2bfloat162(l2, l3);
    }
}

// ======================= launch =============================================
extern "C" void kernel_launch(void* const* d_in, const int* in_sizes, int n_in,
                              void* d_out, int out_size)
{
    const float* ix = (const float*)d_in[0];   // [32, 512, 1024]
    const float* io = (const float*)d_in[1];   // [32, 512, 1024]
    const float* W  = (const float*)d_in[2];   // [1024, 1024]
    const float* bi = (const float*)d_in[3];   // [1024]
    float* out = (float*)d_out;                // [32, 512, 1024]

    u16 *wts, *ms, *ixs, *ios, *ts, *iosT, *ps;
    float *mp, *sc, *wtb, *v;
    cudaGetSymbolAddress((void**)&wts,  g_wts);
    cudaGetSymbolAddress((void**)&mp,   g_mp);
    cudaGetSymbolAddress((void**)&ms,   g_ms);
    cudaGetSymbolAddress((void**)&ixs,  g_ixs);
    cudaGetSymbolAddress((void**)&ios,  g_ios);
    cudaGetSymbolAddress((void**)&ts,   g_ts);
    cudaGetSymbolAddress((void**)&iosT, g_iosT);
    cudaGetSymbolAddress((void**)&sc,   g_sc);
    cudaGetSymbolAddress((void**)&ps,   g_ps);
    cudaGetSymbolAddress((void**)&wtb,  g_wtb);
    cudaGetSymbolAddress((void**)&v,    g_v);

    cudaFuncSetAttribute(gemm_mma<0>, cudaFuncAttributeMaxDynamicSharedMemorySize, GEMM_SMEM);
    cudaFuncSetAttribute(gemm_mma<1>, cudaFuncAttributeMaxDynamicSharedMemorySize, GEMM_SMEM);

    const int Bn = 32, L = 512, D = 1024;
    const int Mproj = Bn * L;  // 16384

    // 0) W^T split
    {
        dim3 g(D / 32, D / 32, 1);
        transpose_split_kernel<<<g, 256>>>(W, wts, D, D, 0, 0);
    }
    // 1) ix split
    split_kernel<<<(Mproj * (long)D) / 1024, 256>>>(ix, ixs, D);
    // 2) M = W^T W  split-K over 4 z-slices (fp32 partials)
    {
        dim3 g(D / 128, D / 128, 4);
        gemm_mma<0><<<g, 128, GEMM_SMEM>>>(wts, wts, nullptr, mp, nullptr,
                                           256, D, 256,
                                           0, 0, (long)D * D, D, 0);
    }
    // 3) wtb = W^T b
    wtb_kernel<<<32, 256>>>(W, bi, wtb);
    // 4) reduce partials + split -> ms
    reduce4_split_kernel<<<(D * (long)D) / 1024, 256>>>(mp, ms);
    // 5) T = ix @ M  (M symmetric -> NT; split output)   [ncu slot 5]
    {
        dim3 g(D / 128, Mproj / 128, 1);
        gemm_mma<1><<<g, 128, GEMM_SMEM>>>(ixs, ms, nullptr, nullptr, ts,
                                           D, D, 0, 0, 0, 0, 2 * D, D);
    }
    // 6) io split
    split_kernel<<<(Mproj * (long)D) / 1024, 256>>>(io, ios, D);
    // 7) v = io @ wtb
    v_kernel<<<Mproj, 256>>>(io, wtb, v);
    // 8) S[b] = T[b] @ io[b]^T  (fp32 out; v added in softmax)
    {
        dim3 g(L / 128, L / 128, Bn);
        gemm_mma<0><<<g, 128, GEMM_SMEM>>>(ts, ios, nullptr, sc, nullptr,
                                           D, D, 0,
                                           (long)L * 2 * D, (long)L * 2 * D,
                                           (long)L * L, L, 0);
    }
    // 9) io^T split per batch (for PV)
    {
        dim3 g(D / 32, L / 32, Bn);
        transpose_split_kernel<<<g, 256>>>(io, iosT, L, D,
                                           (long)L * D, (long)D * 2 * L);
    }
    // 10) warp softmax(S + v) + split probs
    softmax512_split_warp<<<(Bn * L) / 8, 256>>>(sc, v, ps);
    // 11) out[b] = P[b] @ ioT[b]^T
    {
        dim3 g(D / 128, L / 128, Bn);
        gemm_mma<0><<<g, 128, GEMM_SMEM>>>(ps, iosT, nullptr, out, nullptr,
                                           L, L, 0,
                                           (long)L * 2 * L, (long)D * 2 * L,
                                           (long)L * D, D, 0);
    }
}

// round 13
// speedup vs baseline: 1.7249x; 1.0391x over previous
#include <cuda_runtime.h>
#include <cuda_bf16.h>
#include <cstdint>

// ---------------------------------------------------------------------------
// Aligner, algebraic form:
//   softmax(ex@eo^T) == softmax(ix@(W^T W)@io^T + 1 v^T),  v = io @ (W^T b)
//   out = softmax(...) @ io
// Chain: M = W^T W (split-K) ; T = ix M ; S = T io^T ; P = softmax(S+v);
//        out = P io.   mma.sync bf16, 2-term hi/lo split, 3 phases.
// R12: parallel wtb (+atomics), fused io-prep (split+transpose+v in one pass).
// ---------------------------------------------------------------------------

typedef unsigned short u16;  // raw bf16 bits

// ======================= scratch (device globals) ===========================
__device__ u16   g_wts [1024L * 2048];      // W^T split
__device__ float g_mp  [4L * 1024 * 1024];  // M split-K partials (fp32)
__device__ u16   g_ms  [1024L * 2048];      // M = W^T W split
__device__ u16   g_ixs [16384L * 2048];     // ix split
__device__ u16   g_ios [16384L * 2048];     // io split
__device__ u16   g_ts  [16384L * 2048];     // T = ix M split
__device__ u16   g_iosT[32L * 1024 * 1024]; // io^T split per batch
__device__ float g_sc  [32L * 512 * 512];   // scores fp32
__device__ u16   g_ps  [32L * 512 * 1024];  // softmax probs split
__device__ float g_wtb [1024];              // W^T b  (atomic accum)
__device__ float g_v   [16384];             // io @ (W^T b)  (atomic accum)

// ======================= PTX helpers ========================================
__device__ __forceinline__ uint32_t smem_u32(const void* p) {
    uint32_t a;
    asm("{ .reg .u64 t; cvta.to.shared.u64 t, %1; cvt.u32.u64 %0, t; }"
        : "=r"(a) : "l"(p));
    return a;
}

__device__ __forceinline__ void cp_async16(uint32_t saddr, const void* gaddr) {
    asm volatile("cp.async.cg.shared.global [%0], [%1], 16;"
                 :: "r"(saddr), "l"(gaddr) : "memory");
}
__device__ __forceinline__ void cp_commit() {
    asm volatile("cp.async.commit_group;" ::: "memory");
}
template <int N>
__device__ __forceinline__ void cp_wait() {
    asm volatile("cp.async.wait_group %0;" :: "n"(N) : "memory");
}

__device__ __forceinline__ void ldsm_x4(uint32_t* r, uint32_t addr) {
    asm volatile("ldmatrix.sync.aligned.m8n8.x4.shared.b16 {%0,%1,%2,%3}, [%4];"
                 : "=r"(r[0]), "=r"(r[1]), "=r"(r[2]), "=r"(r[3]) : "r"(addr));
}

__device__ __forceinline__ void mma_bf16(float* c, const uint32_t* a,
                                         const uint32_t* b) {
    asm volatile(
        "mma.sync.aligned.m16n8k16.row.col.f32.bf16.bf16.f32 "
        "{%0,%1,%2,%3}, {%4,%5,%6,%7}, {%8,%9}, {%0,%1,%2,%3};"
        : "+f"(c[0]), "+f"(c[1]), "+f"(c[2]), "+f"(c[3])
        : "r"(a[0]), "r"(a[1]), "r"(a[2]), "r"(a[3]), "r"(b[0]), "r"(b[1]));
}

// ======================= split helpers ======================================
__device__ __forceinline__ void split2(float v, __nv_bfloat16& h, __nv_bfloat16& l) {
    h = __float2bfloat16(v);
    l = __float2bfloat16(v - __bfloat162float(h));
}

// fp32 [R, C] -> bf16 [R, 2C] (hi | lo). One float4 per thread.
__global__ void __launch_bounds__(256)
split_kernel(const float* __restrict__ in, u16* __restrict__ out, int C)
{
    const long idx = (long)blockIdx.x * 256 + threadIdx.x;
    const long e = idx * 4;
    const long r = e / C;
    const int  c = (int)(e - r * C);
    const float4 v = *reinterpret_cast<const float4*>(in + e);
    __nv_bfloat16 h0, h1, h2, h3, l0, l1, l2, l3;
    split2(v.x, h0, l0); split2(v.y, h1, l1); split2(v.z, h2, l2); split2(v.w, h3, l3);
    __nv_bfloat16* oh = reinterpret_cast<__nv_bfloat16*>(out + r * (2L * C) + c);
    __nv_bfloat16* ol = reinterpret_cast<__nv_bfloat16*>(out + r * (2L * C) + C + c);
    *reinterpret_cast<__nv_bfloat162*>(oh)     = __halves2bfloat162(h0, h1);
    *reinterpret_cast<__nv_bfloat162*>(oh + 2) = __halves2bfloat162(h2, h3);
    *reinterpret_cast<__nv_bfloat162*>(ol)     = __halves2bfloat162(l0, l1);
    *reinterpret_cast<__nv_bfloat162*>(ol + 2) = __halves2bfloat162(l2, l3);
}

// generic transpose+split (used for W^T): in [R, C] fp32 -> out [C, 2R] split.
__global__ void __launch_bounds__(256)
transpose_split_kernel(const float* __restrict__ in, u16* __restrict__ out,
                       int R, int C, long sIn, long sOut)
{
    __shared__ float t[32][33];
    const int b  = blockIdx.z;
    const int d0 = blockIdx.x * 32;
    const int m0 = blockIdx.y * 32;
    const int tx = threadIdx.x & 31;
    const int ty = threadIdx.x >> 5;
    const float* ib = in + (long)b * sIn;
#pragma unroll
    for (int i = 0; i < 4; i++)
        t[ty + 8 * i][tx] = ib[(long)(m0 + ty + 8 * i) * C + d0 + tx];
    __syncthreads();
    u16* ob = out + (long)b * sOut;
#pragma unroll
    for (int i = 0; i < 4; i++) {
        const int d = d0 + ty + 8 * i;
        const int m = m0 + tx;
        __nv_bfloat16 h, l;
        split2(t[tx][ty + 8 * i], h, l);
        *reinterpret_cast<__nv_bfloat16*>(&ob[(long)d * (2 * R) + m])     = h;
        *reinterpret_cast<__nv_bfloat16*>(&ob[(long)d * (2 * R) + R + m]) = l;
    }
}

// wtb[d] += partial over e-slice. grid (32, 8), wtb pre-zeroed.
__global__ void __launch_bounds__(256)
wtb_kernel(const float* __restrict__ W, const float* __restrict__ b,
           float* __restrict__ wtb)
{
    __shared__ float red[8][32];
    const int tx = threadIdx.x & 31;
    const int ty = threadIdx.x >> 5;
    const int d  = blockIdx.x * 32 + tx;
    const int e0 = blockIdx.y * 128;
    float acc = 0.0f;
    for (int e = e0 + ty; e < e0 + 128; e += 8)
        acc += W[(long)e * 1024 + d] * b[e];
    red[ty][tx] = acc;
    __syncthreads();
    if (ty == 0) {
        float s = red[0][tx];
#pragma unroll
        for (int i = 1; i < 8; i++) s += red[i][tx];
        atomicAdd(&wtb[d], s);
    }
}

// Fused io prep: ONE read of io produces
//   ios  [m, 2048] split, iosT [b][d, 1024] split, v[m] += partial dots.
// grid (1024/32, 512/32, 32), 256 threads. v pre-zeroed; wtb ready.
__global__ void __launch_bounds__(256)
io_prep_kernel(const float* __restrict__ io, const float* __restrict__ wtb,
               u16* __restrict__ ios, u16* __restrict__ iosT,
               float* __restrict__ v)
{
    __shared__ float t[32][33];
    const int b  = blockIdx.z;
    const int d0 = blockIdx.x * 32;
    const int m0 = blockIdx.y * 32;
    const int tx = threadIdx.x & 31;
    const int ty = threadIdx.x >> 5;
    const float* ib = io + (long)b * 512 * 1024;
    const float wv = wtb[d0 + tx];

    float vals[4];
#pragma unroll
    for (int i = 0; i < 4; i++) {
        vals[i] = ib[(long)(m0 + ty + 8 * i) * 1024 + d0 + tx];
        t[ty + 8 * i][tx] = vals[i];
    }

    // ios split: row m = m0+ty+8i (global row b*512+...), col d0+tx
#pragma unroll
    for (int i = 0; i < 4; i++) {
        const long gm = (long)b * 512 + m0 + ty + 8 * i;
        __nv_bfloat16 h, l;
        split2(vals[i], h, l);
        u16* q = ios + gm * 2048 + d0 + tx;
        *reinterpret_cast<__nv_bfloat16*>(q)        = h;
        *reinterpret_cast<__nv_bfloat16*>(q + 1024) = l;
    }

    // v partial: sum over lanes (d) of vals[i]*wtb[d]
#pragma unroll
    for (int i = 0; i < 4; i++) {
        float s = vals[i] * wv;
#pragma unroll
        for (int o = 16; o > 0; o >>= 1)
            s += __shfl_xor_sync(0xFFFFFFFFu, s, o);
        if (tx == 0) atomicAdd(&v[b * 512 + m0 + ty + 8 * i], s);
    }

    __syncthreads();

    // iosT split from smem tile
    u16* ob = iosT + (long)b * 1024 * 1024;
#pragma unroll
    for (int i = 0; i < 4; i++) {
        const int d = d0 + ty + 8 * i;
        const int m = m0 + tx;
        __nv_bfloat16 h, l;
        split2(t[tx][ty + 8 * i], h, l);
        *reinterpret_cast<__nv_bfloat16*>(&ob[(long)d * 1024 + m])       = h;
        *reinterpret_cast<__nv_bfloat16*>(&ob[(long)d * 1024 + 512 + m]) = l;
    }
}

// sum 4 split-K partials of M and split to bf16 hi/lo.
__global__ void __launch_bounds__(256)
reduce4_split_kernel(const float* __restrict__ p, u16* __restrict__ out)
{
    const long e = ((long)blockIdx.x * 256 + threadIdx.x) * 4;
    const long r = e >> 10;
    const int  c = (int)(e & 1023);
    float4 a = *reinterpret_cast<const float4*>(p + e);
    const float4 a1 = *reinterpret_cast<const float4*>(p + 1048576 + e);
    const float4 a2 = *reinterpret_cast<const float4*>(p + 2097152 + e);
    const float4 a3 = *reinterpret_cast<const float4*>(p + 3145728 + e);
    a.x += a1.x + a2.x + a3.x;
    a.y += a1.y + a2.y + a3.y;
    a.z += a1.z + a2.z + a3.z;
    a.w += a1.w + a2.w + a3.w;
    __nv_bfloat16 h0, h1, h2, h3, l0, l1, l2, l3;
    split2(a.x, h0, l0); split2(a.y, h1, l1); split2(a.z, h2, l2); split2(a.w, h3, l3);
    u16* oh = out + r * 2048 + c;
    u16* ol = oh + 1024;
    *reinterpret_cast<__nv_bfloat162*>(oh)     = __halves2bfloat162(h0, h1);
    *reinterpret_cast<__nv_bfloat162*>(oh + 2) = __halves2bfloat162(h2, h3);
    *reinterpret_cast<__nv_bfloat162*>(ol)     = __halves2bfloat162(l0, l1);
    *reinterpret_cast<__nv_bfloat162*>(ol + 2) = __halves2bfloat162(l2, l3);
}

// ======================= mma.sync GEMM engine ===============================
#define LDS_STRIDE 40
#define TILE_BYTES (128 * LDS_STRIDE * 2)
#define STAGE_BYTES (4 * TILE_BYTES)
#define GEMM_SMEM (2 * STAGE_BYTES)

template <int MODE>
__global__ void __launch_bounds__(128, 2)
gemm_mma(const u16* __restrict__ A, const u16* __restrict__ B,
         const float* __restrict__ bias, float* __restrict__ Cf,
         u16* __restrict__ Cs,
         int K, int Kfull, int kPerZ,
         long sA, long sB, long sC, int ldc, int loOff)
{
    extern __shared__ char dynsmem[];

    const int tid  = threadIdx.x;
    const int wid  = tid >> 5;
    const int lane = tid & 31;

    const long bz = blockIdx.z;
    A += bz * sA;
    B += bz * sB;
    const int kbase = (int)bz * kPerZ;
    const int row0 = blockIdx.y * 128;
    const int col0 = blockIdx.x * 128;
    const long lda = 2L * Kfull;

    const int nkc = K / 32;

    const uint32_t sbase = smem_u32(dynsmem);

    const int cr0 = tid >> 2;
    const int cc  = tid & 3;

    const int warp_m = wid & 1;
    const int warp_n = wid >> 1;

    float acc[4][8][4];
#pragma unroll
    for (int mt = 0; mt < 4; mt++)
#pragma unroll
        for (int nt = 0; nt < 8; nt++)
#pragma unroll
            for (int i = 0; i < 4; i++) acc[mt][nt][i] = 0.0f;

    const int a_row = warp_m * 64 + (lane & 15);
    const int a_colb = (lane >> 4) << 3;
    const int b_row = warp_n * 64 + (lane & 7) + ((lane >> 4) << 3);
    const int b_colb = ((lane >> 3) & 1) << 3;

    auto stage_copy = [&](int s, int kc) {
        const uint32_t sb0 = sbase + (uint32_t)s * STAGE_BYTES;
        const int hoff = kbase + kc * 32;
        const int loff = Kfull + kbase + kc * 32;
#pragma unroll
        for (int j = 0; j < 4; j++) {
            const int r = cr0 + 32 * j;
            const uint32_t so = (uint32_t)r * (LDS_STRIDE * 2) + (uint32_t)cc * 16u;
            const u16* arow = A + (long)(row0 + r) * lda + cc * 8;
            const u16* brow = B + (long)(col0 + r) * lda + cc * 8;
            cp_async16(sb0 + 0 * TILE_BYTES + so, arow + hoff);
            cp_async16(sb0 + 1 * TILE_BYTES + so, arow + loff);
            cp_async16(sb0 + 2 * TILE_BYTES + so, brow + hoff);
            cp_async16(sb0 + 3 * TILE_BYTES + so, brow + loff);
        }
        cp_commit();
    };

    stage_copy(0, 0);

    for (int kc = 0; kc < nkc; kc++) {
        cp_wait<0>();
        __syncthreads();

        const uint32_t st = sbase + (uint32_t)(kc & 1) * STAGE_BYTES;
        const uint32_t stAl = st + 1 * TILE_BYTES;
        const uint32_t stBh = st + 2 * TILE_BYTES;
        const uint32_t stBl = st + 3 * TILE_BYTES;

        uint32_t ah[4][4], al[4][4], bh[8][2], bl[8][2];
        {
            const uint32_t a_off =
                (uint32_t)a_row * (LDS_STRIDE * 2) + (uint32_t)a_colb * 2;
            const uint32_t b_off =
                (uint32_t)b_row * (LDS_STRIDE * 2) + (uint32_t)b_colb * 2;
#pragma unroll
            for (int mt = 0; mt < 4; mt++) {
                const uint32_t ao = a_off + (uint32_t)(mt * 16) * (LDS_STRIDE * 2);
                ldsm_x4(ah[mt], st + ao);
                ldsm_x4(al[mt], stAl + ao);
            }
#pragma unroll
            for (int nt2 = 0; nt2 < 4; nt2++) {
                const uint32_t bo = b_off + (uint32_t)(nt2 * 16) * (LDS_STRIDE * 2);
                uint32_t r4[4];
                ldsm_x4(r4, stBh + bo);
                bh[2 * nt2][0] = r4[0]; bh[2 * nt2][1] = r4[1];
                bh[2 * nt2 + 1][0] = r4[2]; bh[2 * nt2 + 1][1] = r4[3];
                uint32_t s4[4];
                ldsm_x4(s4, stBl + bo);
                bl[2 * nt2][0] = s4[0]; bl[2 * nt2][1] = s4[1];
                bl[2 * nt2 + 1][0] = s4[2]; bl[2 * nt2 + 1][1] = s4[3];
            }
        }

        if (kc + 1 < nkc) stage_copy((kc + 1) & 1, kc + 1);

#pragma unroll
        for (int mt = 0; mt < 4; mt++)
#pragma unroll
            for (int nt = 0; nt < 8; nt++)
                mma_bf16(acc[mt][nt], ah[mt], bh[nt]);
#pragma unroll
        for (int mt = 0; mt < 4; mt++)
#pragma unroll
            for (int nt = 0; nt < 8; nt++)
                mma_bf16(acc[mt][nt], ah[mt], bl[nt]);
#pragma unroll
        for (int mt = 0; mt < 4; mt++)
#pragma unroll
            for (int nt = 0; nt < 8; nt++)
                mma_bf16(acc[mt][nt], al[mt], bh[nt]);

        {
            const uint32_t a_off =
                (uint32_t)a_row * (LDS_STRIDE * 2) + (uint32_t)(16 + a_colb) * 2;
            const uint32_t b_off =
                (uint32_t)b_row * (LDS_STRIDE * 2) + (uint32_t)(16 + b_colb) * 2;
#pragma unroll
            for (int mt = 0; mt < 4; mt++) {
                const uint32_t ao = a_off + (uint32_t)(mt * 16) * (LDS_STRIDE * 2);
                ldsm_x4(ah[mt], st + ao);
                ldsm_x4(al[mt], stAl + ao);
            }
#pragma unroll
            for (int nt2 = 0; nt2 < 4; nt2++) {
                const uint32_t bo = b_off + (uint32_t)(nt2 * 16) * (LDS_STRIDE * 2);
                uint32_t r4[4];
                ldsm_x4(r4, stBh + bo);
                bh[2 * nt2][0] = r4[0]; bh[2 * nt2][1] = r4[1];
                bh[2 * nt2 + 1][0] = r4[2]; bh[2 * nt2 + 1][1] = r4[3];
                uint32_t s4[4];
                ldsm_x4(s4, stBl + bo);
                bl[2 * nt2][0] = s4[0]; bl[2 * nt2][1] = s4[1];
                bl[2 * nt2 + 1][0] = s4[2]; bl[2 * nt2 + 1][1] = s4[3];
            }
        }
#pragma unroll
        for (int mt = 0; mt < 4; mt++)
#pragma unroll
            for (int nt = 0; nt < 8; nt++)
                mma_bf16(acc[mt][nt], ah[mt], bh[nt]);
#pragma unroll
        for (int mt = 0; mt < 4; mt++)
#pragma unroll
            for (int nt = 0; nt < 8; nt++)
                mma_bf16(acc[mt][nt], ah[mt], bl[nt]);
#pragma unroll
        for (int mt = 0; mt < 4; mt++)
#pragma unroll
            for (int nt = 0; nt < 8; nt++)
                mma_bf16(acc[mt][nt], al[mt], bh[nt]);
    }

    // ---- epilogue ----
    const int er0 = row0 + warp_m * 64 + (lane >> 2);
    const int ec0 = col0 + warp_n * 64 + (lane & 3) * 2;
#pragma unroll
    for (int mt = 0; mt < 4; mt++) {
#pragma unroll
        for (int nt = 0; nt < 8; nt++) {
            const int r0 = er0 + mt * 16;
            const int r1 = r0 + 8;
            const int c  = ec0 + nt * 8;
            if (MODE == 0) {
                float2 v0, v1;
                v0.x = acc[mt][nt][0]; v0.y = acc[mt][nt][1];
                v1.x = acc[mt][nt][2]; v1.y = acc[mt][nt][3];
                *reinterpret_cast<float2*>(Cf + bz * sC + (long)r0 * ldc + c) = v0;
                *reinterpret_cast<float2*>(Cf + bz * sC + (long)r1 * ldc + c) = v1;
            } else {
                const float b0 = bias ? bias[c] : 0.0f;
                const float b1 = bias ? bias[c + 1] : 0.0f;
                __nv_bfloat16 h0, h1, l0, l1;
                u16* q0 = Cs + (long)r0 * ldc + c;
                split2(acc[mt][nt][0] + b0, h0, l0);
                split2(acc[mt][nt][1] + b1, h1, l1);
                *reinterpret_cast<__nv_bfloat162*>(q0) = __halves2bfloat162(h0, h1);
                *reinterpret_cast<__nv_bfloat162*>(q0 + loOff) = __halves2bfloat162(l0, l1);
                u16* q1 = Cs + (long)r1 * ldc + c;
                split2(acc[mt][nt][2] + b0, h0, l0);
                split2(acc[mt][nt][3] + b1, h1, l1);
                *reinterpret_cast<__nv_bfloat162*>(q1) = __halves2bfloat162(h0, h1);
                *reinterpret_cast<__nv_bfloat162*>(q1 + loOff) = __halves2bfloat162(l0, l1);
            }
        }
    }
}

// ======================= warp softmax(+v) + split ===========================
__global__ void __launch_bounds__(256)
softmax512_split_warp(const float* __restrict__ S, const float* __restrict__ v,
                      u16* __restrict__ P)
{
    const int gw   = (blockIdx.x * 256 + threadIdx.x) >> 5;
    const int lane = threadIdx.x & 31;
    const float* row = S + (long)gw * 512;
    const float* vb  = v + ((gw >> 9) << 9);
    u16* prow = P + (long)gw * 1024;

    float x[16];
    float mx = -1e30f;
#pragma unroll
    for (int i = 0; i < 4; i++) {
        const int c = i * 128 + lane * 4;
        const float4 a = *reinterpret_cast<const float4*>(row + c);
        const float4 w = *reinterpret_cast<const float4*>(vb + c);
        x[4 * i + 0] = a.x + w.x;
        x[4 * i + 1] = a.y + w.y;
        x[4 * i + 2] = a.z + w.z;
        x[4 * i + 3] = a.w + w.w;
        mx = fmaxf(mx, fmaxf(fmaxf(x[4 * i], x[4 * i + 1]),
                             fmaxf(x[4 * i + 2], x[4 * i + 3])));
    }
#pragma unroll
    for (int o = 16; o > 0; o >>= 1)
        mx = fmaxf(mx, __shfl_xor_sync(0xFFFFFFFFu, mx, o));

    float sum = 0.0f;
#pragma unroll
    for (int j = 0; j < 16; j++) {
        x[j] = __expf(x[j] - mx);
        sum += x[j];
    }
#pragma unroll
    for (int o = 16; o > 0; o >>= 1)
        sum += __shfl_xor_sync(0xFFFFFFFFu, sum, o);
    const float inv = 1.0f / sum;

#pragma unroll
    for (int i = 0; i < 4; i++) {
        const int c = i * 128 + lane * 4;
        __nv_bfloat16 h0, h1, h2, h3, l0, l1, l2, l3;
        split2(x[4 * i + 0] * inv, h0, l0);
        split2(x[4 * i + 1] * inv, h1, l1);
        split2(x[4 * i + 2] * inv, h2, l2);
        split2(x[4 * i + 3] * inv, h3, l3);
        u16* oh = prow + c;
        u16* ol = prow + 512 + c;
        *reinterpret_cast<__nv_bfloat162*>(oh)     = __halves2bfloat162(h0, h1);
        *reinterpret_cast<__nv_bfloat162*>(oh + 2) = __halves2bfloat162(h2, h3);
        *reinterpret_cast<__nv_bfloat162*>(ol)     = __halves2bfloat162(l0, l1);
        *reinterpret_cast<__nv_bfloat162*>(ol + 2) = __halves2bfloat162(l2, l3);
    }
}

// ======================= launch =============================================
extern "C" void kernel_launch(void* const* d_in, const int* in_sizes, int n_in,
                              void* d_out, int out_size)
{
    const float* ix = (const float*)d_in[0];   // [32, 512, 1024]
    const float* io = (const float*)d_in[1];   // [32, 512, 1024]
    const float* W  = (const float*)d_in[2];   // [1024, 1024]
    const float* bi = (const float*)d_in[3];   // [1024]
    float* out = (float*)d_out;                // [32, 512, 1024]

    u16 *wts, *ms, *ixs, *ios, *ts, *iosT, *ps;
    float *mp, *sc, *wtb, *v;
    cudaGetSymbolAddress((void**)&wts,  g_wts);
    cudaGetSymbolAddress((void**)&mp,   g_mp);
    cudaGetSymbolAddress((void**)&ms,   g_ms);
    cudaGetSymbolAddress((void**)&ixs,  g_ixs);
    cudaGetSymbolAddress((void**)&ios,  g_ios);
    cudaGetSymbolAddress((void**)&ts,   g_ts);
    cudaGetSymbolAddress((void**)&iosT, g_iosT);
    cudaGetSymbolAddress((void**)&sc,   g_sc);
    cudaGetSymbolAddress((void**)&ps,   g_ps);
    cudaGetSymbolAddress((void**)&wtb,  g_wtb);
    cudaGetSymbolAddress((void**)&v,    g_v);

    cudaFuncSetAttribute(gemm_mma<0>, cudaFuncAttributeMaxDynamicSharedMemorySize, GEMM_SMEM);
    cudaFuncSetAttribute(gemm_mma<1>, cudaFuncAttributeMaxDynamicSharedMemorySize, GEMM_SMEM);

    const int Bn = 32, L = 512, D = 1024;
    const int Mproj = Bn * L;  // 16384

    // zero atomic accumulators (memset nodes, not kernel launches)
    cudaMemsetAsync(wtb, 0, 1024 * sizeof(float));
    cudaMemsetAsync(v,   0, 16384 * sizeof(float));

    // 0) wtb = W^T b  (parallel over 8 e-slices, atomic)
    {
        dim3 g(32, 8, 1);
        wtb_kernel<<<g, 256>>>(W, bi, wtb);
    }
    // 1) W^T split
    {
        dim3 g(D / 32, D / 32, 1);
        transpose_split_kernel<<<g, 256>>>(W, wts, D, D, 0, 0);
    }
    // 2) ix split
    split_kernel<<<(Mproj * (long)D) / 1024, 256>>>(ix, ixs, D);
    // 3) M = W^T W  split-K over 4 z-slices (fp32 partials)
    {
        dim3 g(D / 128, D / 128, 4);
        gemm_mma<0><<<g, 128, GEMM_SMEM>>>(wts, wts, nullptr, mp, nullptr,
                                           256, D, 256,
                                           0, 0, (long)D * D, D, 0);
    }
    // 4) reduce partials + split -> ms
    reduce4_split_kernel<<<(D * (long)D) / 1024, 256>>>(mp, ms);
    // 5) T = ix @ M  (split output)   [ncu kernel-launch slot 5]
    {
        dim3 g(D / 128, Mproj / 128, 1);
        gemm_mma<1><<<g, 128, GEMM_SMEM>>>(ixs, ms, nullptr, nullptr, ts,
                                           D, D, 0, 0, 0, 0, 2 * D, D);
    }
    // 6) fused io prep: ios + iosT + v in one pass over io
    {
        dim3 g(D / 32, L / 32, Bn);
        io_prep_kernel<<<g, 256>>>(io, wtb, ios, iosT, v);
    }
    // 7) S[b] = T[b] @ io[b]^T  (fp32 out; v added in softmax)
    {
        dim3 g(L / 128, L / 128, Bn);
        gemm_mma<0><<<g, 128, GEMM_SMEM>>>(ts, ios, nullptr, sc, nullptr,
                                           D, D, 0,
                                           (long)L * 2 * D, (long)L * 2 * D,
                                           (long)L * L, L, 0);
    }
    // 8) warp softmax(S + v) + split probs
    softmax512_split_warp<<<(Bn * L) / 8, 256>>>(sc, v, ps);
    // 9) out[b] = P[b] @ ioT[b]^T
    {
        dim3 g(D / 128, L / 128, Bn);
        gemm_mma<0><<<g, 128, GEMM_SMEM>>>(ps, iosT, nullptr, out, nullptr,
                                           L, L, 0,
                                           (long)L * 2 * L, (long)D * 2 * L,
                                           (long)L * D, D, 0);
    }
}

// round 14
// speedup vs baseline: 1.7783x; 1.0309x over previous
#include <cuda_runtime.h>
#include <cuda_bf16.h>
#include <cstdint>

// ---------------------------------------------------------------------------
// Aligner, algebraic form:
//   softmax(ex@eo^T) == softmax(ix@(W^T W)@io^T + 1 v^T),  v = io @ (W^T b)
//   out = softmax(...) @ io
// Chain: M = W^T W (split-K z=8) ; T = ix M ; S = T io^T ;
//        P = softmax(S+v) ; out = P io  (NN via ldmatrix.trans — no io^T copy)
// All GEMMs: mma.sync bf16, 2-term hi/lo split, 3 phases, fp32 accumulate.
// ---------------------------------------------------------------------------

typedef unsigned short u16;  // raw bf16 bits

// ======================= scratch (device globals) ===========================
__device__ u16   g_wts [1024L * 2048];      // W^T split
__device__ float g_mp  [8L * 1024 * 1024];  // M split-K partials (fp32, z=8)
__device__ u16   g_ms  [1024L * 2048];      // M = W^T W split
__device__ u16   g_ixs [16384L * 2048];     // ix split
__device__ u16   g_ios [16384L * 2048];     // io split
__device__ u16   g_ts  [16384L * 2048];     // T = ix M split
__device__ float g_sc  [32L * 512 * 512];   // scores fp32
__device__ u16   g_ps  [32L * 512 * 1024];  // softmax probs split
__device__ float g_wtb [1024];              // W^T b  (atomic accum)
__device__ float g_v   [16384];             // io @ (W^T b)  (atomic accum)

// ======================= PTX helpers ========================================
__device__ __forceinline__ uint32_t smem_u32(const void* p) {
    uint32_t a;
    asm("{ .reg .u64 t; cvta.to.shared.u64 t, %1; cvt.u32.u64 %0, t; }"
        : "=r"(a) : "l"(p));
    return a;
}

__device__ __forceinline__ void cp_async16(uint32_t saddr, const void* gaddr) {
    asm volatile("cp.async.cg.shared.global [%0], [%1], 16;"
                 :: "r"(saddr), "l"(gaddr) : "memory");
}
__device__ __forceinline__ void cp_commit() {
    asm volatile("cp.async.commit_group;" ::: "memory");
}
template <int N>
__device__ __forceinline__ void cp_wait() {
    asm volatile("cp.async.wait_group %0;" :: "n"(N) : "memory");
}

__device__ __forceinline__ void ldsm_x4(uint32_t* r, uint32_t addr) {
    asm volatile("ldmatrix.sync.aligned.m8n8.x4.shared.b16 {%0,%1,%2,%3}, [%4];"
                 : "=r"(r[0]), "=r"(r[1]), "=r"(r[2]), "=r"(r[3]) : "r"(addr));
}
__device__ __forceinline__ void ldsm_x4_trans(uint32_t* r, uint32_t addr) {
    asm volatile("ldmatrix.sync.aligned.m8n8.x4.trans.shared.b16 {%0,%1,%2,%3}, [%4];"
                 : "=r"(r[0]), "=r"(r[1]), "=r"(r[2]), "=r"(r[3]) : "r"(addr));
}

__device__ __forceinline__ void mma_bf16(float* c, const uint32_t* a,
                                         const uint32_t* b) {
    asm volatile(
        "mma.sync.aligned.m16n8k16.row.col.f32.bf16.bf16.f32 "
        "{%0,%1,%2,%3}, {%4,%5,%6,%7}, {%8,%9}, {%0,%1,%2,%3};"
        : "+f"(c[0]), "+f"(c[1]), "+f"(c[2]), "+f"(c[3])
        : "r"(a[0]), "r"(a[1]), "r"(a[2]), "r"(a[3]), "r"(b[0]), "r"(b[1]));
}

// ======================= split helpers ======================================
__device__ __forceinline__ void split2(float v, __nv_bfloat16& h, __nv_bfloat16& l) {
    h = __float2bfloat16(v);
    l = __float2bfloat16(v - __bfloat162float(h));
}

// fp32 [R, C] -> bf16 [R, 2C] (hi | lo). One float4 per thread.
__global__ void __launch_bounds__(256)
split_kernel(const float* __restrict__ in, u16* __restrict__ out, int C)
{
    const long idx = (long)blockIdx.x * 256 + threadIdx.x;
    const long e = idx * 4;
    const long r = e / C;
    const int  c = (int)(e - r * C);
    const float4 v = *reinterpret_cast<const float4*>(in + e);
    __nv_bfloat16 h0, h1, h2, h3, l0, l1, l2, l3;
    split2(v.x, h0, l0); split2(v.y, h1, l1); split2(v.z, h2, l2); split2(v.w, h3, l3);
    __nv_bfloat16* oh = reinterpret_cast<__nv_bfloat16*>(out + r * (2L * C) + c);
    __nv_bfloat16* ol = reinterpret_cast<__nv_bfloat16*>(out + r * (2L * C) + C + c);
    *reinterpret_cast<__nv_bfloat162*>(oh)     = __halves2bfloat162(h0, h1);
    *reinterpret_cast<__nv_bfloat162*>(oh + 2) = __halves2bfloat162(h2, h3);
    *reinterpret_cast<__nv_bfloat162*>(ol)     = __halves2bfloat162(l0, l1);
    *reinterpret_cast<__nv_bfloat162*>(ol + 2) = __halves2bfloat162(l2, l3);
}

// io split + v accumulation (C = 1024 fixed). One float4 per thread.
// A warp covers 128 contiguous d of ONE row -> shfl reduce + 1 atomic.
__global__ void __launch_bounds__(256)
split_v_kernel(const float* __restrict__ in, const float* __restrict__ wtb,
               u16* __restrict__ out, float* __restrict__ v)
{
    const long idx = (long)blockIdx.x * 256 + threadIdx.x;
    const long e = idx * 4;
    const long r = e >> 10;
    const int  c = (int)(e & 1023);
    const float4 a = *reinterpret_cast<const float4*>(in + e);
    const float4 w = *reinterpret_cast<const float4*>(wtb + c);

    __nv_bfloat16 h0, h1, h2, h3, l0, l1, l2, l3;
    split2(a.x, h0, l0); split2(a.y, h1, l1); split2(a.z, h2, l2); split2(a.w, h3, l3);
    u16* oh = out + r * 2048 + c;
    u16* ol = oh + 1024;
    *reinterpret_cast<__nv_bfloat162*>(oh)     = __halves2bfloat162(h0, h1);
    *reinterpret_cast<__nv_bfloat162*>(oh + 2) = __halves2bfloat162(h2, h3);
    *reinterpret_cast<__nv_bfloat162*>(ol)     = __halves2bfloat162(l0, l1);
    *reinterpret_cast<__nv_bfloat162*>(ol + 2) = __halves2bfloat162(l2, l3);

    float s = a.x * w.x + a.y * w.y + a.z * w.z + a.w * w.w;
#pragma unroll
    for (int o = 16; o > 0; o >>= 1)
        s += __shfl_xor_sync(0xFFFFFFFFu, s, o);
    if ((threadIdx.x & 31) == 0) atomicAdd(&v[r], s);
}

// generic transpose+split (used for W^T): in [R, C] fp32 -> out [C, 2R] split.
__global__ void __launch_bounds__(256)
transpose_split_kernel(const float* __restrict__ in, u16* __restrict__ out,
                       int R, int C, long sIn, long sOut)
{
    __shared__ float t[32][33];
    const int b  = blockIdx.z;
    const int d0 = blockIdx.x * 32;
    const int m0 = blockIdx.y * 32;
    const int tx = threadIdx.x & 31;
    const int ty = threadIdx.x >> 5;
    const float* ib = in + (long)b * sIn;
#pragma unroll
    for (int i = 0; i < 4; i++)
        t[ty + 8 * i][tx] = ib[(long)(m0 + ty + 8 * i) * C + d0 + tx];
    __syncthreads();
    u16* ob = out + (long)b * sOut;
#pragma unroll
    for (int i = 0; i < 4; i++) {
        const int d = d0 + ty + 8 * i;
        const int m = m0 + tx;
        __nv_bfloat16 h, l;
        split2(t[tx][ty + 8 * i], h, l);
        *reinterpret_cast<__nv_bfloat16*>(&ob[(long)d * (2 * R) + m])     = h;
        *reinterpret_cast<__nv_bfloat16*>(&ob[(long)d * (2 * R) + R + m]) = l;
    }
}

// wtb[d] += partial over e-slice. grid (32, 8), wtb pre-zeroed.
__global__ void __launch_bounds__(256)
wtb_kernel(const float* __restrict__ W, const float* __restrict__ b,
           float* __restrict__ wtb)
{
    __shared__ float red[8][32];
    const int tx = threadIdx.x & 31;
    const int ty = threadIdx.x >> 5;
    const int d  = blockIdx.x * 32 + tx;
    const int e0 = blockIdx.y * 128;
    float acc = 0.0f;
    for (int e = e0 + ty; e < e0 + 128; e += 8)
        acc += W[(long)e * 1024 + d] * b[e];
    red[ty][tx] = acc;
    __syncthreads();
    if (ty == 0) {
        float s = red[0][tx];
#pragma unroll
        for (int i = 1; i < 8; i++) s += red[i][tx];
        atomicAdd(&wtb[d], s);
    }
}

// sum 8 split-K partials of M and split to bf16 hi/lo.
__global__ void __launch_bounds__(256)
reduce8_split_kernel(const float* __restrict__ p, u16* __restrict__ out)
{
    const long e = ((long)blockIdx.x * 256 + threadIdx.x) * 4;
    const long r = e >> 10;
    const int  c = (int)(e & 1023);
    float4 a = *reinterpret_cast<const float4*>(p + e);
#pragma unroll
    for (int s = 1; s < 8; s++) {
        const float4 b = *reinterpret_cast<const float4*>(p + (long)s * 1048576 + e);
        a.x += b.x; a.y += b.y; a.z += b.z; a.w += b.w;
    }
    __nv_bfloat16 h0, h1, h2, h3, l0, l1, l2, l3;
    split2(a.x, h0, l0); split2(a.y, h1, l1); split2(a.z, h2, l2); split2(a.w, h3, l3);
    u16* oh = out + r * 2048 + c;
    u16* ol = oh + 1024;
    *reinterpret_cast<__nv_bfloat162*>(oh)     = __halves2bfloat162(h0, h1);
    *reinterpret_cast<__nv_bfloat162*>(oh + 2) = __halves2bfloat162(h2, h3);
    *reinterpret_cast<__nv_bfloat162*>(ol)     = __halves2bfloat162(l0, l1);
    *reinterpret_cast<__nv_bfloat162*>(ol + 2) = __halves2bfloat162(l2, l3);
}

// ======================= mma.sync GEMM engine ===============================
// NT (BTRANS=0): C = A[M,2Kfull] (*) B[N,2Kfull], B row-major [N,K].
// NN (BTRANS=1): C = A[M,2Kfull] (*) B[Krows, ldb], B row-major [K,N];
//                hi cols at col0.., lo cols at col0+loOff.. ; fragments via
//                ldmatrix.trans (exactly reproduces the NT fragment layout).
// 3 bf16 phases, fp32 accumulate. CTA 128x128, 4 warps (2Mx2N of 64x64),
// 2-stage cp.async, 2 CTAs/SM.
#define LDS_STRIDE 40
#define BSTRIDE 136                          // NN B tile: 32 x 136 u16
#define TILE_BYTES (128 * LDS_STRIDE * 2)
#define STAGE_BYTES (4 * TILE_BYTES)
#define GEMM_SMEM (2 * STAGE_BYTES)

template <int MODE, int BTRANS>
__global__ void __launch_bounds__(128, 2)
gemm_mma(const u16* __restrict__ A, const u16* __restrict__ B,
         const float* __restrict__ bias, float* __restrict__ Cf,
         u16* __restrict__ Cs,
         int K, int Kfull, int kPerZ,
         long sA, long sB, long sC, int ldc, int loOff, int ldb)
{
    extern __shared__ char dynsmem[];

    const int tid  = threadIdx.x;
    const int wid  = tid >> 5;
    const int lane = tid & 31;

    const long bz = blockIdx.z;
    A += bz * sA;
    B += bz * sB;
    const int kbase = (int)bz * kPerZ;
    const int row0 = blockIdx.y * 128;
    const int col0 = blockIdx.x * 128;
    const long lda = 2L * Kfull;

    const int nkc = K / 32;

    const uint32_t sbase = smem_u32(dynsmem);

    const int cr0 = tid >> 2;
    const int cc  = tid & 3;

    const int warp_m = wid & 1;
    const int warp_n = wid >> 1;

    float acc[4][8][4];
#pragma unroll
    for (int mt = 0; mt < 4; mt++)
#pragma unroll
        for (int nt = 0; nt < 8; nt++)
#pragma unroll
            for (int i = 0; i < 4; i++) acc[mt][nt][i] = 0.0f;

    const int a_row = warp_m * 64 + (lane & 15);
    const int a_colb = (lane >> 4) << 3;
    // NT B-frag lane mapping
    const int b_row = warp_n * 64 + (lane & 7) + ((lane >> 4) << 3);
    const int b_colb = ((lane >> 3) & 1) << 3;
    // NN (trans) B-frag lane mapping: k-row and n-offset per lane
    const int bk = (lane & 7) + (((lane >> 3) & 1) << 3);   // 0..15
    const int bn = warp_n * 64 + ((lane >> 4) << 3);        // n base

    auto stage_copy = [&](int s, int kc) {
        const uint32_t sb0 = sbase + (uint32_t)s * STAGE_BYTES;
        const int hoff = kbase + kc * 32;
        const int loff = Kfull + kbase + kc * 32;
#pragma unroll
        for (int j = 0; j < 4; j++) {
            const int r = cr0 + 32 * j;
            const uint32_t so = (uint32_t)r * (LDS_STRIDE * 2) + (uint32_t)cc * 16u;
            const u16* arow = A + (long)(row0 + r) * lda + cc * 8;
            cp_async16(sb0 + 0 * TILE_BYTES + so, arow + hoff);
            cp_async16(sb0 + 1 * TILE_BYTES + so, arow + loff);
        }
        if (!BTRANS) {
#pragma unroll
            for (int j = 0; j < 4; j++) {
                const int r = cr0 + 32 * j;
                const uint32_t so = (uint32_t)r * (LDS_STRIDE * 2) + (uint32_t)cc * 16u;
                const u16* brow = B + (long)(col0 + r) * lda + cc * 8;
                cp_async16(sb0 + 2 * TILE_BYTES + so, brow + hoff);
                cp_async16(sb0 + 3 * TILE_BYTES + so, brow + loff);
            }
        } else {
            // B tile: 32 k-rows x 128 n-cols (hi & lo)
#pragma unroll
            for (int j = 0; j < 4; j++) {
                const int vv = tid + 128 * j;        // 0..511
                const int krow = vv >> 4;            // 0..31
                const int vc   = vv & 15;            // 16B col
                const uint32_t so = (uint32_t)krow * (BSTRIDE * 2) + (uint32_t)vc * 16u;
                const u16* brow = B + (long)(kbase + kc * 32 + krow) * ldb
                                    + col0 + vc * 8;
                cp_async16(sb0 + 2 * TILE_BYTES + so, brow);
                cp_async16(sb0 + 3 * TILE_BYTES + so, brow + loOff);
            }
        }
        cp_commit();
    };

    stage_copy(0, 0);

    for (int kc = 0; kc < nkc; kc++) {
        cp_wait<0>();
        __syncthreads();

        const uint32_t st = sbase + (uint32_t)(kc & 1) * STAGE_BYTES;
        const uint32_t stAl = st + 1 * TILE_BYTES;
        const uint32_t stBh = st + 2 * TILE_BYTES;
        const uint32_t stBl = st + 3 * TILE_BYTES;

        uint32_t ah[4][4], al[4][4], bh[8][2], bl[8][2];
        // ---- kk = 0 fragment loads (before next-stage copy) ----
        {
            const uint32_t a_off =
                (uint32_t)a_row * (LDS_STRIDE * 2) + (uint32_t)a_colb * 2;
#pragma unroll
            for (int mt = 0; mt < 4; mt++) {
                const uint32_t ao = a_off + (uint32_t)(mt * 16) * (LDS_STRIDE * 2);
                ldsm_x4(ah[mt], st + ao);
                ldsm_x4(al[mt], stAl + ao);
            }
#pragma unroll
            for (int nt2 = 0; nt2 < 4; nt2++) {
                uint32_t r4[4], s4[4];
                if (!BTRANS) {
                    const uint32_t bo =
                        (uint32_t)(b_row + nt2 * 16) * (LDS_STRIDE * 2) +
                        (uint32_t)b_colb * 2;
                    ldsm_x4(r4, stBh + bo);
                    ldsm_x4(s4, stBl + bo);
                } else {
                    const uint32_t bo =
                        (uint32_t)bk * (BSTRIDE * 2) +
                        (uint32_t)(bn + nt2 * 16) * 2;
                    ldsm_x4_trans(r4, stBh + bo);
                    ldsm_x4_trans(s4, stBl + bo);
                }
                bh[2 * nt2][0] = r4[0]; bh[2 * nt2][1] = r4[1];
                bh[2 * nt2 + 1][0] = r4[2]; bh[2 * nt2 + 1][1] = r4[3];
                bl[2 * nt2][0] = s4[0]; bl[2 * nt2][1] = s4[1];
                bl[2 * nt2 + 1][0] = s4[2]; bl[2 * nt2 + 1][1] = s4[3];
            }
        }

        if (kc + 1 < nkc) stage_copy((kc + 1) & 1, kc + 1);

#pragma unroll
        for (int mt = 0; mt < 4; mt++)
#pragma unroll
            for (int nt = 0; nt < 8; nt++)
                mma_bf16(acc[mt][nt], ah[mt], bh[nt]);
#pragma unroll
        for (int mt = 0; mt < 4; mt++)
#pragma unroll
            for (int nt = 0; nt < 8; nt++)
                mma_bf16(acc[mt][nt], ah[mt], bl[nt]);
#pragma unroll
        for (int mt = 0; mt < 4; mt++)
#pragma unroll
            for (int nt = 0; nt < 8; nt++)
                mma_bf16(acc[mt][nt], al[mt], bh[nt]);

        // ---- kk = 1 ----
        {
            const uint32_t a_off =
                (uint32_t)a_row * (LDS_STRIDE * 2) + (uint32_t)(16 + a_colb) * 2;
#pragma unroll
            for (int mt = 0; mt < 4; mt++) {
                const uint32_t ao = a_off + (uint32_t)(mt * 16) * (LDS_STRIDE * 2);
                ldsm_x4(ah[mt], st + ao);
                ldsm_x4(al[mt], stAl + ao);
            }
#pragma unroll
            for (int nt2 = 0; nt2 < 4; nt2++) {
                uint32_t r4[4], s4[4];
                if (!BTRANS) {
                    const uint32_t bo =
                        (uint32_t)(b_row + nt2 * 16) * (LDS_STRIDE * 2) +
                        (uint32_t)(16 + b_colb) * 2;
                    ldsm_x4(r4, stBh + bo);
                    ldsm_x4(s4, stBl + bo);
                } else {
                    const uint32_t bo =
                        (uint32_t)(16 + bk) * (BSTRIDE * 2) +
                        (uint32_t)(bn + nt2 * 16) * 2;
                    ldsm_x4_trans(r4, stBh + bo);
                    ldsm_x4_trans(s4, stBl + bo);
                }
                bh[2 * nt2][0] = r4[0]; bh[2 * nt2][1] = r4[1];
                bh[2 * nt2 + 1][0] = r4[2]; bh[2 * nt2 + 1][1] = r4[3];
                bl[2 * nt2][0] = s4[0]; bl[2 * nt2][1] = s4[1];
                bl[2 * nt2 + 1][0] = s4[2]; bl[2 * nt2 + 1][1] = s4[3];
            }
        }
#pragma unroll
        for (int mt = 0; mt < 4; mt++)
#pragma unroll
            for (int nt = 0; nt < 8; nt++)
                mma_bf16(acc[mt][nt], ah[mt], bh[nt]);
#pragma unroll
        for (int mt = 0; mt < 4; mt++)
#pragma unroll
            for (int nt = 0; nt < 8; nt++)
                mma_bf16(acc[mt][nt], ah[mt], bl[nt]);
#pragma unroll
        for (int mt = 0; mt < 4; mt++)
#pragma unroll
            for (int nt = 0; nt < 8; nt++)
                mma_bf16(acc[mt][nt], al[mt], bh[nt]);
    }

    // ---- epilogue ----
    const int er0 = row0 + warp_m * 64 + (lane >> 2);
    const int ec0 = col0 + warp_n * 64 + (lane & 3) * 2;
#pragma unroll
    for (int mt = 0; mt < 4; mt++) {
#pragma unroll
        for (int nt = 0; nt < 8; nt++) {
            const int r0 = er0 + mt * 16;
            const int r1 = r0 + 8;
            const int c  = ec0 + nt * 8;
            if (MODE == 0) {
                float2 v0, v1;
                v0.x = acc[mt][nt][0]; v0.y = acc[mt][nt][1];
                v1.x = acc[mt][nt][2]; v1.y = acc[mt][nt][3];
                *reinterpret_cast<float2*>(Cf + bz * sC + (long)r0 * ldc + c) = v0;
                *reinterpret_cast<float2*>(Cf + bz * sC + (long)r1 * ldc + c) = v1;
            } else {
                const float b0 = bias ? bias[c] : 0.0f;
                const float b1 = bias ? bias[c + 1] : 0.0f;
                __nv_bfloat16 h0, h1, l0, l1;
                u16* q0 = Cs + (long)r0 * ldc + c;
                split2(acc[mt][nt][0] + b0, h0, l0);
                split2(acc[mt][nt][1] + b1, h1, l1);
                *reinterpret_cast<__nv_bfloat162*>(q0) = __halves2bfloat162(h0, h1);
                *reinterpret_cast<__nv_bfloat162*>(q0 + loOff) = __halves2bfloat162(l0, l1);
                u16* q1 = Cs + (long)r1 * ldc + c;
                split2(acc[mt][nt][2] + b0, h0, l0);
                split2(acc[mt][nt][3] + b1, h1, l1);
                *reinterpret_cast<__nv_bfloat162*>(q1) = __halves2bfloat162(h0, h1);
                *reinterpret_cast<__nv_bfloat162*>(q1 + loOff) = __halves2bfloat162(l0, l1);
            }
        }
    }
}

// ======================= warp softmax(+v) + split ===========================
__global__ void __launch_bounds__(256)
softmax512_split_warp(const float* __restrict__ S, const float* __restrict__ v,
                      u16* __restrict__ P)
{
    const int gw   = (blockIdx.x * 256 + threadIdx.x) >> 5;
    const int lane = threadIdx.x & 31;
    const float* row = S + (long)gw * 512;
    const float* vb  = v + ((gw >> 9) << 9);
    u16* prow = P + (long)gw * 1024;

    float x[16];
    float mx = -1e30f;
#pragma unroll
    for (int i = 0; i < 4; i++) {
        const int c = i * 128 + lane * 4;
        const float4 a = *reinterpret_cast<const float4*>(row + c);
        const float4 w = *reinterpret_cast<const float4*>(vb + c);
        x[4 * i + 0] = a.x + w.x;
        x[4 * i + 1] = a.y + w.y;
        x[4 * i + 2] = a.z + w.z;
        x[4 * i + 3] = a.w + w.w;
        mx = fmaxf(mx, fmaxf(fmaxf(x[4 * i], x[4 * i + 1]),
                             fmaxf(x[4 * i + 2], x[4 * i + 3])));
    }
#pragma unroll
    for (int o = 16; o > 0; o >>= 1)
        mx = fmaxf(mx, __shfl_xor_sync(0xFFFFFFFFu, mx, o));

    float sum = 0.0f;
#pragma unroll
    for (int j = 0; j < 16; j++) {
        x[j] = __expf(x[j] - mx);
        sum += x[j];
    }
#pragma unroll
    for (int o = 16; o > 0; o >>= 1)
        sum += __shfl_xor_sync(0xFFFFFFFFu, sum, o);
    const float inv = 1.0f / sum;

#pragma unroll
    for (int i = 0; i < 4; i++) {
        const int c = i * 128 + lane * 4;
        __nv_bfloat16 h0, h1, h2, h3, l0, l1, l2, l3;
        split2(x[4 * i + 0] * inv, h0, l0);
        split2(x[4 * i + 1] * inv, h1, l1);
        split2(x[4 * i + 2] * inv, h2, l2);
        split2(x[4 * i + 3] * inv, h3, l3);
        u16* oh = prow + c;
        u16* ol = prow + 512 + c;
        *reinterpret_cast<__nv_bfloat162*>(oh)     = __halves2bfloat162(h0, h1);
        *reinterpret_cast<__nv_bfloat162*>(oh + 2) = __halves2bfloat162(h2, h3);
        *reinterpret_cast<__nv_bfloat162*>(ol)     = __halves2bfloat162(l0, l1);
        *reinterpret_cast<__nv_bfloat162*>(ol + 2) = __halves2bfloat162(l2, l3);
    }
}

// ======================= launch =============================================
extern "C" void kernel_launch(void* const* d_in, const int* in_sizes, int n_in,
                              void* d_out, int out_size)
{
    const float* ix = (const float*)d_in[0];   // [32, 512, 1024]
    const float* io = (const float*)d_in[1];   // [32, 512, 1024]
    const float* W  = (const float*)d_in[2];   // [1024, 1024]
    const float* bi = (const float*)d_in[3];   // [1024]
    float* out = (float*)d_out;                // [32, 512, 1024]

    u16 *wts, *ms, *ixs, *ios, *ts, *ps;
    float *mp, *sc, *wtb, *v;
    cudaGetSymbolAddress((void**)&wts,  g_wts);
    cudaGetSymbolAddress((void**)&mp,   g_mp);
    cudaGetSymbolAddress((void**)&ms,   g_ms);
    cudaGetSymbolAddress((void**)&ixs,  g_ixs);
    cudaGetSymbolAddress((void**)&ios,  g_ios);
    cudaGetSymbolAddress((void**)&ts,   g_ts);
    cudaGetSymbolAddress((void**)&sc,   g_sc);
    cudaGetSymbolAddress((void**)&ps,   g_ps);
    cudaGetSymbolAddress((void**)&wtb,  g_wtb);
    cudaGetSymbolAddress((void**)&v,    g_v);

    cudaFuncSetAttribute(gemm_mma<0, 0>, cudaFuncAttributeMaxDynamicSharedMemorySize, GEMM_SMEM);
    cudaFuncSetAttribute(gemm_mma<1, 0>, cudaFuncAttributeMaxDynamicSharedMemorySize, GEMM_SMEM);
    cudaFuncSetAttribute(gemm_mma<0, 1>, cudaFuncAttributeMaxDynamicSharedMemorySize, GEMM_SMEM);

    const int Bn = 32, L = 512, D = 1024;
    const int Mproj = Bn * L;  // 16384

    // zero atomic accumulators
    cudaMemsetAsync(wtb, 0, 1024 * sizeof(float));
    cudaMemsetAsync(v,   0, 16384 * sizeof(float));

    // 0) wtb = W^T b
    {
        dim3 g(32, 8, 1);
        wtb_kernel<<<g, 256>>>(W, bi, wtb);
    }
    // 1) W^T split
    {
        dim3 g(D / 32, D / 32, 1);
        transpose_split_kernel<<<g, 256>>>(W, wts, D, D, 0, 0);
    }
    // 2) ix split
    split_kernel<<<(Mproj * (long)D) / 1024, 256>>>(ix, ixs, D);
    // 3) M = W^T W  split-K over 8 z-slices (fp32 partials)
    {
        dim3 g(D / 128, D / 128, 8);
        gemm_mma<0, 0><<<g, 128, GEMM_SMEM>>>(wts, wts, nullptr, mp, nullptr,
                                              128, D, 128,
                                              0, 0, (long)D * D, D, 0, 0);
    }
    // 4) reduce partials + split -> ms
    reduce8_split_kernel<<<(D * (long)D) / 1024, 256>>>(mp, ms);
    // 5) T = ix @ M  (split output)
    {
        dim3 g(D / 128, Mproj / 128, 1);
        gemm_mma<1, 0><<<g, 128, GEMM_SMEM>>>(ixs, ms, nullptr, nullptr, ts,
                                              D, D, 0, 0, 0, 0, 2 * D, D, 0);
    }
    // 6) io split + v  (one pass over io)
    split_v_kernel<<<(Mproj * (long)D) / 1024, 256>>>(io, wtb, ios, v);
    // 7) S[b] = T[b] @ io[b]^T  (NT; fp32 out; v added in softmax)
    {
        dim3 g(L / 128, L / 128, Bn);
        gemm_mma<0, 0><<<g, 128, GEMM_SMEM>>>(ts, ios, nullptr, sc, nullptr,
                                              D, D, 0,
                                              (long)L * 2 * D, (long)L * 2 * D,
                                              (long)L * L, L, 0, 0);
    }
    // 8) warp softmax(S + v) + split probs
    softmax512_split_warp<<<(Bn * L) / 8, 256>>>(sc, v, ps);
    // 9) out[b] = P[b] @ io[b]  (NN via ldmatrix.trans; B = ios, lo at +1024)
    {
        dim3 g(D / 128, L / 128, Bn);
        gemm_mma<0, 1><<<g, 128, GEMM_SMEM>>>(ps, ios, nullptr, out, nullptr,
                                              L, L, 0,
                                              (long)L * 2 * L, (long)L * 2 * D,
                                              (long)L * D, D, 1024, 2 * D);
    }
}